// round 3
// baseline (speedup 1.0000x reference)
#include <cuda_runtime.h>

// ---------------- fixed problem shapes ----------------
#define N_NODES 100000
#define D 64
#define E_EDGES 1600000
#define MSG_H 128
#define MSG_OUT 64
#define NODE_H 128
#define LN_EPS 1e-5f

// ---------------- device scratch (allowed: __device__ globals) ----------
__device__ __align__(16) float g_Ps[(size_t)N_NODES * 128];  // nodes @ W1[0:64,:]
__device__ __align__(16) float g_Pr[(size_t)N_NODES * 128];  // nodes @ W1[64:128,:] + b1
__device__ __align__(16) float g_agg[(size_t)N_NODES * 64];  // segment-sum of messages

// =====================================================================
// Kernel 0: zero aggregation buffer
// =====================================================================
__global__ void zero_agg_kernel() {
    float4* p = reinterpret_cast<float4*>(g_agg);
    const int n4 = N_NODES * 64 / 4;
    for (int i = blockIdx.x * blockDim.x + threadIdx.x; i < n4; i += gridDim.x * blockDim.x)
        p[i] = make_float4(0.f, 0.f, 0.f, 0.f);
}

// =====================================================================
// Kernel 1: node projections. 256 threads, 2 nodes per iteration.
//   thread t: node = n0 + (t>>7), col c = t&127; computes Ps and Pr.
// =====================================================================
__global__ __launch_bounds__(256, 3)
void proj_kernel(const float* __restrict__ nodes,
                 const float* __restrict__ msg_W1,
                 const float* __restrict__ msg_b1)
{
    extern __shared__ float sm[];
    float* sW = sm;              // [128][128]: rows 0..63 sender dims, 64..127 receiver dims
    float* sN = sm + 128 * 128;  // [2][64] node rows

    const int tid = threadIdx.x;
    for (int i = tid; i < 128 * 128; i += 256) sW[i] = msg_W1[i];
    __syncthreads();

    const int sub = tid >> 7;      // which of the 2 nodes
    const int c   = tid & 127;     // output column
    const float bias = msg_b1[c];

    const int numPairs = N_NODES / 2;
    for (int p = blockIdx.x; p < numPairs; p += gridDim.x) {
        const int n0 = p * 2;
        if (tid < 128) sN[tid] = nodes[(size_t)n0 * 64 + tid];
        __syncthreads();

        float as = 0.f, ar = 0.f;
        const float* nr = &sN[sub * 64];
        #pragma unroll 8
        for (int k = 0; k < 64; ++k) {
            const float a = nr[k];
            as = fmaf(a, sW[k * 128 + c], as);
            ar = fmaf(a, sW[(64 + k) * 128 + c], ar);
        }
        const int n = n0 + sub;
        g_Ps[(size_t)n * 128 + c] = as;
        g_Pr[(size_t)n * 128 + c] = ar + bias;
        __syncthreads();
    }
}

// =====================================================================
// Kernel 2: edge message MLP + scatter-add. 64-edge tiles, 256 threads,
// 2 edges per thread (pair), persistent grid-stride. Smem: 115.2KB -> 2 CTA/SM.
//   h   = relu(Ps[s] + Pr[r] + edges @ W1_edge)   [64 x 128]
//   msg = relu(h @ W2 + b2)                       [64 x 64]
//   agg[r] += msg   (atomicAdd -> REDG)
// =====================================================================
#define ES_W1   (64 * 128)
#define ES_W2   (128 * 64)
#define ES_E    (64 * 64)
#define ES_H    (64 * 130)
#define EDGE_SMEM ((ES_W1 + ES_W2 + ES_E + ES_H) * 4)

__global__ __launch_bounds__(256, 2)
void edge_kernel(const float* __restrict__ edges,
                 const int* __restrict__ senders,
                 const int* __restrict__ receivers,
                 const float* __restrict__ msg_W1,
                 const float* __restrict__ msg_W2,
                 const float* __restrict__ msg_b2)
{
    extern __shared__ float sm[];
    float* sW1 = sm;               // [64][128]  (W1 rows 128..191: edge-feature part)
    float* sW2 = sW1 + ES_W1;      // [128][64]
    float* sE  = sW2 + ES_W2;      // [64][64], XOR-swizzled rows
    float* sH  = sE  + ES_E;       // [64][130]

    const int tid = threadIdx.x;
    for (int i = tid; i < ES_W1; i += 256)
        sW1[i] = msg_W1[(128 + (i >> 7)) * 128 + (i & 127)];
    for (int i = tid; i < ES_W2; i += 256)
        sW2[i] = msg_W2[i];

    const int pair = tid >> 3;          // 0..31  (handles edges 2*pair, 2*pair+1)
    const int sub  = tid & 7;           // 0..7
    const int c0   = sub * 16;          // GEMM1 column base
    const int o0   = sub * 8;           // GEMM2 output base
    const int swz  = (pair & 3) * 8;    // edge-tile bank swizzle (floats)

    float rb2[8];
    #pragma unroll
    for (int j = 0; j < 8; ++j) rb2[j] = __ldg(&msg_b2[o0 + j]);

    const int numTiles = E_EDGES / 64;
    for (int tile = blockIdx.x; tile < numTiles; tile += gridDim.x) {
        const int e0 = tile * 64;
        __syncthreads();   // previous iteration's smem reads complete
        // ---- load edge tile (64x64 floats = 1024 float4), XOR-swizzled ----
        #pragma unroll
        for (int i = 0; i < 4; ++i) {
            const int idx = tid + i * 256;        // float4 index in tile
            const int row = idx >> 4;
            const int c4  = idx & 15;
            reinterpret_cast<float4*>(sE)[row * 16 + (c4 ^ (row & 6))] =
                reinterpret_cast<const float4*>(edges)[(size_t)e0 * 16 + idx];
        }
        const int eA = e0 + 2 * pair;
        const int s0 = __ldg(&senders[eA]);
        const int s1 = __ldg(&senders[eA + 1]);
        const int r0 = __ldg(&receivers[eA]);
        const int r1 = __ldg(&receivers[eA + 1]);
        __syncthreads();

        // ---- GEMM1: 2 edges x 16 cols, K=64; acc init = Ps[s] + Pr[r] ----
        float acc0[16], acc1[16];
        {
            const float4* ps0 = reinterpret_cast<const float4*>(&g_Ps[(size_t)s0 * 128 + c0]);
            const float4* pr0 = reinterpret_cast<const float4*>(&g_Pr[(size_t)r0 * 128 + c0]);
            const float4* ps1 = reinterpret_cast<const float4*>(&g_Ps[(size_t)s1 * 128 + c0]);
            const float4* pr1 = reinterpret_cast<const float4*>(&g_Pr[(size_t)r1 * 128 + c0]);
            #pragma unroll
            for (int q = 0; q < 4; ++q) {
                float4 a = ps0[q], b = pr0[q];
                acc0[q*4+0]=a.x+b.x; acc0[q*4+1]=a.y+b.y; acc0[q*4+2]=a.z+b.z; acc0[q*4+3]=a.w+b.w;
                float4 cc = ps1[q], d = pr1[q];
                acc1[q*4+0]=cc.x+d.x; acc1[q*4+1]=cc.y+d.y; acc1[q*4+2]=cc.z+d.z; acc1[q*4+3]=cc.w+d.w;
            }
        }
        const float* er0 = &sE[(2 * pair) * 64];
        const float* er1 = &sE[(2 * pair + 1) * 64];
        #pragma unroll 4
        for (int k = 0; k < 64; ++k) {
            const float a0 = er0[k ^ swz];
            const float a1 = er1[k ^ swz];
            float w[16];
            const float* wr = &sW1[k * 128 + c0];
            *reinterpret_cast<float4*>(&w[0])  = *reinterpret_cast<const float4*>(wr);
            *reinterpret_cast<float4*>(&w[4])  = *reinterpret_cast<const float4*>(wr + 4);
            *reinterpret_cast<float4*>(&w[8])  = *reinterpret_cast<const float4*>(wr + 8);
            *reinterpret_cast<float4*>(&w[12]) = *reinterpret_cast<const float4*>(wr + 12);
            #pragma unroll
            for (int j = 0; j < 16; ++j) {
                acc0[j] = fmaf(a0, w[j], acc0[j]);
                acc1[j] = fmaf(a1, w[j], acc1[j]);
            }
        }
        // ---- ReLU, store h ----
        {
            float* h0 = &sH[(2 * pair) * 130 + c0];
            float* h1 = &sH[(2 * pair + 1) * 130 + c0];
            #pragma unroll
            for (int j = 0; j < 16; ++j) {
                h0[j] = fmaxf(acc0[j], 0.f);
                h1[j] = fmaxf(acc1[j], 0.f);
            }
        }
        __syncthreads();

        // ---- GEMM2: 2 edges x 8 outs, K=128 ----
        float m0[8], m1[8];
        #pragma unroll
        for (int j = 0; j < 8; ++j) { m0[j] = rb2[j]; m1[j] = rb2[j]; }
        const float* h0 = &sH[(2 * pair) * 130];
        const float* h1 = &sH[(2 * pair + 1) * 130];
        #pragma unroll 4
        for (int k = 0; k < 128; ++k) {
            const float a0 = h0[k];
            const float a1 = h1[k];
            float w[8];
            *reinterpret_cast<float4*>(&w[0]) = *reinterpret_cast<const float4*>(&sW2[k * 64 + o0]);
            *reinterpret_cast<float4*>(&w[4]) = *reinterpret_cast<const float4*>(&sW2[k * 64 + o0 + 4]);
            #pragma unroll
            for (int j = 0; j < 8; ++j) {
                m0[j] = fmaf(a0, w[j], m0[j]);
                m1[j] = fmaf(a1, w[j], m1[j]);
            }
        }
        // ---- ReLU + scatter-add ----
        float* d0 = &g_agg[(size_t)r0 * 64 + o0];
        float* d1 = &g_agg[(size_t)r1 * 64 + o0];
        #pragma unroll
        for (int j = 0; j < 8; ++j) atomicAdd(&d0[j], fmaxf(m0[j], 0.f));
        #pragma unroll
        for (int j = 0; j < 8; ++j) atomicAdd(&d1[j], fmaxf(m1[j], 0.f));
    }
}

// =====================================================================
// Kernel 3: node update MLP + LayerNorm + residual. 16-node tiles,
// 256 threads, persistent 148 blocks. Smem ~120.8KB -> 1 CTA/SM.
// =====================================================================
#define NS_W1 (128 * 128)
#define NS_W2 (128 * 64)
#define NS_X  (16 * 132)
#define NS_H  (16 * 132)
#define NS_Y  (16 * 68)
#define NODE_SMEM ((NS_W1 + NS_W2 + 128 + 64 + 64 + 64 + NS_X + NS_H + NS_Y) * 4)

__global__ __launch_bounds__(256, 1)
void node_kernel(const float* __restrict__ nodes,
                 const float* __restrict__ node_W1,
                 const float* __restrict__ node_b1,
                 const float* __restrict__ node_W2,
                 const float* __restrict__ node_b2,
                 const float* __restrict__ ln_scale,
                 const float* __restrict__ ln_offset,
                 float* __restrict__ out)
{
    extern __shared__ float sm[];
    float* sW1 = sm;               // [128][128]
    float* sW2 = sW1 + NS_W1;      // [128][64]
    float* sB1 = sW2 + NS_W2;      // [128]
    float* sB2 = sB1 + 128;        // [64]
    float* sS  = sB2 + 64;         // [64]
    float* sO  = sS + 64;          // [64]
    float* sX  = sO + 64;          // [16][132]
    float* sH  = sX + NS_X;        // [16][132]
    float* sY  = sH + NS_H;        // [16][68]

    const int tid = threadIdx.x;
    for (int i = tid; i < NS_W1; i += 256) sW1[i] = node_W1[i];
    for (int i = tid; i < NS_W2; i += 256) sW2[i] = node_W2[i];
    if (tid < 128) sB1[tid] = node_b1[tid];
    if (tid < 64) { sB2[tid] = node_b2[tid]; sS[tid] = ln_scale[tid]; sO[tid] = ln_offset[tid]; }

    const int i16 = tid >> 4;   // node within tile (GEMM mapping)
    const int g16 = tid & 15;
    const int wid = tid >> 5, lid = tid & 31;
    const int numTiles = N_NODES / 16;

    for (int tile = blockIdx.x; tile < numTiles; tile += gridDim.x) {
        const int n0 = tile * 16;
        __syncthreads();
        for (int idx = tid; idx < 16 * 128; idx += 256) {
            const int i = idx >> 7, c = idx & 127;
            sX[i * 132 + c] = (c < 64) ? nodes[(size_t)(n0 + i) * 64 + c]
                                       : g_agg[(size_t)(n0 + i) * 64 + (c - 64)];
        }
        __syncthreads();

        // GEMM1: 16 nodes x 128 cols, 8 cols/thread, K=128
        {
            const int c0 = g16 * 8;
            float acc[8];
            #pragma unroll
            for (int j = 0; j < 8; ++j) acc[j] = sB1[c0 + j];
            const float* xr = &sX[i16 * 132];
            #pragma unroll 4
            for (int k = 0; k < 128; ++k) {
                const float a = xr[k];
                float w[8];
                *reinterpret_cast<float4*>(&w[0]) = *reinterpret_cast<const float4*>(&sW1[k * 128 + c0]);
                *reinterpret_cast<float4*>(&w[4]) = *reinterpret_cast<const float4*>(&sW1[k * 128 + c0 + 4]);
                #pragma unroll
                for (int j = 0; j < 8; ++j) acc[j] = fmaf(a, w[j], acc[j]);
            }
            float* hr = &sH[i16 * 132 + c0];
            #pragma unroll
            for (int j = 0; j < 8; ++j) hr[j] = fmaxf(acc[j], 0.f);
        }
        __syncthreads();

        // GEMM2: 16 nodes x 64 outs, 4 outs/thread, K=128
        {
            const int c0 = g16 * 4;
            float acc[4];
            #pragma unroll
            for (int j = 0; j < 4; ++j) acc[j] = sB2[c0 + j];
            const float* hr = &sH[i16 * 132];
            #pragma unroll 4
            for (int k = 0; k < 128; ++k) {
                const float a = hr[k];
                float4 w = *reinterpret_cast<const float4*>(&sW2[k * 64 + c0]);
                acc[0] = fmaf(a, w.x, acc[0]);
                acc[1] = fmaf(a, w.y, acc[1]);
                acc[2] = fmaf(a, w.z, acc[2]);
                acc[3] = fmaf(a, w.w, acc[3]);
            }
            float* yr = &sY[i16 * 68 + c0];
            #pragma unroll
            for (int j = 0; j < 4; ++j) yr[j] = acc[j];
        }
        __syncthreads();

        // LayerNorm + residual: warp handles 2 nodes
        #pragma unroll
        for (int q = 0; q < 2; ++q) {
            const int i = wid * 2 + q;
            const float v0 = sY[i * 68 + lid];
            const float v1 = sY[i * 68 + 32 + lid];
            float s  = v0 + v1;
            float sq = v0 * v0 + v1 * v1;
            #pragma unroll
            for (int off = 16; off; off >>= 1) {
                s  += __shfl_xor_sync(0xffffffffu, s,  off);
                sq += __shfl_xor_sync(0xffffffffu, sq, off);
            }
            const float mean = s * (1.f / 64.f);
            const float var  = sq * (1.f / 64.f) - mean * mean;
            const float rstd = rsqrtf(var + LN_EPS);
            const size_t n = (size_t)(n0 + i);
            out[n * 64 + lid]      = sX[i * 132 + lid]      + (v0 - mean) * rstd * sS[lid]      + sO[lid];
            out[n * 64 + 32 + lid] = sX[i * 132 + 32 + lid] + (v1 - mean) * rstd * sS[32 + lid] + sO[32 + lid];
        }
    }
}

// =====================================================================
extern "C" void kernel_launch(void* const* d_in, const int* in_sizes, int n_in,
                              void* d_out, int out_size) {
    (void)in_sizes; (void)n_in; (void)out_size;
    const float* nodes     = (const float*)d_in[0];
    const float* edges     = (const float*)d_in[1];
    const int*   senders   = (const int*)d_in[2];
    const int*   receivers = (const int*)d_in[3];
    const float* msg_W1    = (const float*)d_in[4];
    const float* msg_b1    = (const float*)d_in[5];
    const float* msg_W2    = (const float*)d_in[6];
    const float* msg_b2    = (const float*)d_in[7];
    const float* node_W1   = (const float*)d_in[8];
    const float* node_b1   = (const float*)d_in[9];
    const float* node_W2   = (const float*)d_in[10];
    const float* node_b2   = (const float*)d_in[11];
    const float* ln_scale  = (const float*)d_in[12];
    const float* ln_offset = (const float*)d_in[13];
    float* out = (float*)d_out;

    static bool attr_done = false;
    if (!attr_done) {
        cudaFuncSetAttribute(proj_kernel, cudaFuncAttributeMaxDynamicSharedMemorySize, (128 * 128 + 128) * 4);
        cudaFuncSetAttribute(edge_kernel, cudaFuncAttributeMaxDynamicSharedMemorySize, EDGE_SMEM);
        cudaFuncSetAttribute(node_kernel, cudaFuncAttributeMaxDynamicSharedMemorySize, NODE_SMEM);
        attr_done = true;
    }

    zero_agg_kernel<<<256, 256>>>();
    proj_kernel<<<444, 256, (128 * 128 + 128) * 4>>>(nodes, msg_W1, msg_b1);
    edge_kernel<<<296, 256, EDGE_SMEM>>>(edges, senders, receivers, msg_W1, msg_W2, msg_b2);
    node_kernel<<<148, 256, NODE_SMEM>>>(nodes, node_W1, node_b1, node_W2, node_b2,
                                         ln_scale, ln_offset, out);
}

// round 4
// speedup vs baseline: 1.0027x; 1.0027x over previous
#include <cuda_runtime.h>

// ---------------- fixed problem shapes ----------------
#define N_NODES 100000
#define D 64
#define E_EDGES 1600000
#define MSG_H 128
#define MSG_OUT 64
#define NODE_H 128
#define LN_EPS 1e-5f

// ---------------- device scratch (allowed: __device__ globals) ----------
__device__ __align__(16) float g_Ps[(size_t)N_NODES * 128];  // nodes @ W1[0:64,:]
__device__ __align__(16) float g_Pr[(size_t)N_NODES * 128];  // nodes @ W1[64:128,:] + b1
__device__ __align__(16) float g_agg[(size_t)N_NODES * 64];  // segment-sum of messages

// =====================================================================
// Kernel 0: zero aggregation buffer
// =====================================================================
__global__ void zero_agg_kernel() {
    float4* p = reinterpret_cast<float4*>(g_agg);
    const int n4 = N_NODES * 64 / 4;
    for (int i = blockIdx.x * blockDim.x + threadIdx.x; i < n4; i += gridDim.x * blockDim.x)
        p[i] = make_float4(0.f, 0.f, 0.f, 0.f);
}

// =====================================================================
// Kernel 1: node projections. 256 threads, 2 nodes per iteration.
//   thread t: node = n0 + (t>>7), col c = t&127; computes Ps and Pr.
// =====================================================================
__global__ __launch_bounds__(256, 3)
void proj_kernel(const float* __restrict__ nodes,
                 const float* __restrict__ msg_W1,
                 const float* __restrict__ msg_b1)
{
    extern __shared__ float sm[];
    float* sW = sm;              // [128][128]: rows 0..63 sender dims, 64..127 receiver dims
    float* sN = sm + 128 * 128;  // [2][64] node rows

    const int tid = threadIdx.x;
    for (int i = tid; i < 128 * 128; i += 256) sW[i] = msg_W1[i];
    __syncthreads();

    const int sub = tid >> 7;      // which of the 2 nodes
    const int c   = tid & 127;     // output column
    const float bias = msg_b1[c];

    const int numPairs = N_NODES / 2;
    for (int p = blockIdx.x; p < numPairs; p += gridDim.x) {
        const int n0 = p * 2;
        if (tid < 128) sN[tid] = nodes[(size_t)n0 * 64 + tid];
        __syncthreads();

        float as = 0.f, ar = 0.f;
        const float* nr = &sN[sub * 64];
        #pragma unroll 8
        for (int k = 0; k < 64; ++k) {
            const float a = nr[k];
            as = fmaf(a, sW[k * 128 + c], as);
            ar = fmaf(a, sW[(64 + k) * 128 + c], ar);
        }
        const int n = n0 + sub;
        g_Ps[(size_t)n * 128 + c] = as;
        g_Pr[(size_t)n * 128 + c] = ar + bias;
        __syncthreads();
    }
}

// =====================================================================
// Kernel 2: edge message MLP + scatter-add. 64-edge tiles, 256 threads,
// 2 edges per thread (pair), persistent grid-stride. Smem: 115.2KB -> 2 CTA/SM.
//   h   = relu(Ps[s] + Pr[r] + edges @ W1_edge)   [64 x 128]
//   msg = relu(h @ W2 + b2)                       [64 x 64]
//   agg[r] += msg   (atomicAdd -> REDG)
// =====================================================================
#define ES_W1   (64 * 128)
#define ES_W2   (128 * 64)
#define ES_E    (64 * 64)
#define ES_H    (64 * 130)
#define EDGE_SMEM ((ES_W1 + ES_W2 + ES_E + ES_H) * 4)

__global__ __launch_bounds__(256, 2)
void edge_kernel(const float* __restrict__ edges,
                 const int* __restrict__ senders,
                 const int* __restrict__ receivers,
                 const float* __restrict__ msg_W1,
                 const float* __restrict__ msg_W2,
                 const float* __restrict__ msg_b2)
{
    extern __shared__ float sm[];
    float* sW1 = sm;               // [64][128]  (W1 rows 128..191: edge-feature part)
    float* sW2 = sW1 + ES_W1;      // [128][64]
    float* sE  = sW2 + ES_W2;      // [64][64], XOR-swizzled rows
    float* sH  = sE  + ES_E;       // [64][130]

    const int tid = threadIdx.x;
    for (int i = tid; i < ES_W1; i += 256)
        sW1[i] = msg_W1[(128 + (i >> 7)) * 128 + (i & 127)];
    for (int i = tid; i < ES_W2; i += 256)
        sW2[i] = msg_W2[i];

    const int pair = tid >> 3;          // 0..31  (handles edges 2*pair, 2*pair+1)
    const int sub  = tid & 7;           // 0..7
    const int c0   = sub * 16;          // GEMM1 column base
    const int o0   = sub * 8;           // GEMM2 output base
    const int swz  = (pair & 3) * 8;    // edge-tile bank swizzle (floats)

    float rb2[8];
    #pragma unroll
    for (int j = 0; j < 8; ++j) rb2[j] = __ldg(&msg_b2[o0 + j]);

    const int numTiles = E_EDGES / 64;
    for (int tile = blockIdx.x; tile < numTiles; tile += gridDim.x) {
        const int e0 = tile * 64;
        __syncthreads();   // previous iteration's smem reads complete
        // ---- load edge tile (64x64 floats = 1024 float4), XOR-swizzled ----
        #pragma unroll
        for (int i = 0; i < 4; ++i) {
            const int idx = tid + i * 256;        // float4 index in tile
            const int row = idx >> 4;
            const int c4  = idx & 15;
            reinterpret_cast<float4*>(sE)[row * 16 + (c4 ^ (row & 6))] =
                reinterpret_cast<const float4*>(edges)[(size_t)e0 * 16 + idx];
        }
        const int eA = e0 + 2 * pair;
        const int s0 = __ldg(&senders[eA]);
        const int s1 = __ldg(&senders[eA + 1]);
        const int r0 = __ldg(&receivers[eA]);
        const int r1 = __ldg(&receivers[eA + 1]);
        __syncthreads();

        // ---- GEMM1: 2 edges x 16 cols, K=64; acc init = Ps[s] + Pr[r] ----
        float acc0[16], acc1[16];
        {
            const float4* ps0 = reinterpret_cast<const float4*>(&g_Ps[(size_t)s0 * 128 + c0]);
            const float4* pr0 = reinterpret_cast<const float4*>(&g_Pr[(size_t)r0 * 128 + c0]);
            const float4* ps1 = reinterpret_cast<const float4*>(&g_Ps[(size_t)s1 * 128 + c0]);
            const float4* pr1 = reinterpret_cast<const float4*>(&g_Pr[(size_t)r1 * 128 + c0]);
            #pragma unroll
            for (int q = 0; q < 4; ++q) {
                float4 a = ps0[q], b = pr0[q];
                acc0[q*4+0]=a.x+b.x; acc0[q*4+1]=a.y+b.y; acc0[q*4+2]=a.z+b.z; acc0[q*4+3]=a.w+b.w;
                float4 cc = ps1[q], d = pr1[q];
                acc1[q*4+0]=cc.x+d.x; acc1[q*4+1]=cc.y+d.y; acc1[q*4+2]=cc.z+d.z; acc1[q*4+3]=cc.w+d.w;
            }
        }
        const float* er0 = &sE[(2 * pair) * 64];
        const float* er1 = &sE[(2 * pair + 1) * 64];
        #pragma unroll 4
        for (int k = 0; k < 64; ++k) {
            const float a0 = er0[k ^ swz];
            const float a1 = er1[k ^ swz];
            float w[16];
            const float* wr = &sW1[k * 128 + c0];
            *reinterpret_cast<float4*>(&w[0])  = *reinterpret_cast<const float4*>(wr);
            *reinterpret_cast<float4*>(&w[4])  = *reinterpret_cast<const float4*>(wr + 4);
            *reinterpret_cast<float4*>(&w[8])  = *reinterpret_cast<const float4*>(wr + 8);
            *reinterpret_cast<float4*>(&w[12]) = *reinterpret_cast<const float4*>(wr + 12);
            #pragma unroll
            for (int j = 0; j < 16; ++j) {
                acc0[j] = fmaf(a0, w[j], acc0[j]);
                acc1[j] = fmaf(a1, w[j], acc1[j]);
            }
        }
        // ---- ReLU, store h ----
        {
            float* h0 = &sH[(2 * pair) * 130 + c0];
            float* h1 = &sH[(2 * pair + 1) * 130 + c0];
            #pragma unroll
            for (int j = 0; j < 16; ++j) {
                h0[j] = fmaxf(acc0[j], 0.f);
                h1[j] = fmaxf(acc1[j], 0.f);
            }
        }
        __syncthreads();

        // ---- GEMM2: 2 edges x 8 outs, K=128 ----
        float m0[8], m1[8];
        #pragma unroll
        for (int j = 0; j < 8; ++j) { m0[j] = rb2[j]; m1[j] = rb2[j]; }
        const float* h0 = &sH[(2 * pair) * 130];
        const float* h1 = &sH[(2 * pair + 1) * 130];
        #pragma unroll 4
        for (int k = 0; k < 128; ++k) {
            const float a0 = h0[k];
            const float a1 = h1[k];
            float w[8];
            *reinterpret_cast<float4*>(&w[0]) = *reinterpret_cast<const float4*>(&sW2[k * 64 + o0]);
            *reinterpret_cast<float4*>(&w[4]) = *reinterpret_cast<const float4*>(&sW2[k * 64 + o0 + 4]);
            #pragma unroll
            for (int j = 0; j < 8; ++j) {
                m0[j] = fmaf(a0, w[j], m0[j]);
                m1[j] = fmaf(a1, w[j], m1[j]);
            }
        }
        // ---- ReLU + scatter-add ----
        float* d0 = &g_agg[(size_t)r0 * 64 + o0];
        float* d1 = &g_agg[(size_t)r1 * 64 + o0];
        #pragma unroll
        for (int j = 0; j < 8; ++j) atomicAdd(&d0[j], fmaxf(m0[j], 0.f));
        #pragma unroll
        for (int j = 0; j < 8; ++j) atomicAdd(&d1[j], fmaxf(m1[j], 0.f));
    }
}

// =====================================================================
// Kernel 3: node update MLP + LayerNorm + residual. 16-node tiles,
// 256 threads, persistent 148 blocks. Smem ~120.8KB -> 1 CTA/SM.
// =====================================================================
#define NS_W1 (128 * 128)
#define NS_W2 (128 * 64)
#define NS_X  (16 * 132)
#define NS_H  (16 * 132)
#define NS_Y  (16 * 68)
#define NODE_SMEM ((NS_W1 + NS_W2 + 128 + 64 + 64 + 64 + NS_X + NS_H + NS_Y) * 4)

__global__ __launch_bounds__(256, 1)
void node_kernel(const float* __restrict__ nodes,
                 const float* __restrict__ node_W1,
                 const float* __restrict__ node_b1,
                 const float* __restrict__ node_W2,
                 const float* __restrict__ node_b2,
                 const float* __restrict__ ln_scale,
                 const float* __restrict__ ln_offset,
                 float* __restrict__ out)
{
    extern __shared__ float sm[];
    float* sW1 = sm;               // [128][128]
    float* sW2 = sW1 + NS_W1;      // [128][64]
    float* sB1 = sW2 + NS_W2;      // [128]
    float* sB2 = sB1 + 128;        // [64]
    float* sS  = sB2 + 64;         // [64]
    float* sO  = sS + 64;          // [64]
    float* sX  = sO + 64;          // [16][132]
    float* sH  = sX + NS_X;        // [16][132]
    float* sY  = sH + NS_H;        // [16][68]

    const int tid = threadIdx.x;
    for (int i = tid; i < NS_W1; i += 256) sW1[i] = node_W1[i];
    for (int i = tid; i < NS_W2; i += 256) sW2[i] = node_W2[i];
    if (tid < 128) sB1[tid] = node_b1[tid];
    if (tid < 64) { sB2[tid] = node_b2[tid]; sS[tid] = ln_scale[tid]; sO[tid] = ln_offset[tid]; }

    const int i16 = tid >> 4;   // node within tile (GEMM mapping)
    const int g16 = tid & 15;
    const int wid = tid >> 5, lid = tid & 31;
    const int numTiles = N_NODES / 16;

    for (int tile = blockIdx.x; tile < numTiles; tile += gridDim.x) {
        const int n0 = tile * 16;
        __syncthreads();
        for (int idx = tid; idx < 16 * 128; idx += 256) {
            const int i = idx >> 7, c = idx & 127;
            sX[i * 132 + c] = (c < 64) ? nodes[(size_t)(n0 + i) * 64 + c]
                                       : g_agg[(size_t)(n0 + i) * 64 + (c - 64)];
        }
        __syncthreads();

        // GEMM1: 16 nodes x 128 cols, 8 cols/thread, K=128
        {
            const int c0 = g16 * 8;
            float acc[8];
            #pragma unroll
            for (int j = 0; j < 8; ++j) acc[j] = sB1[c0 + j];
            const float* xr = &sX[i16 * 132];
            #pragma unroll 4
            for (int k = 0; k < 128; ++k) {
                const float a = xr[k];
                float w[8];
                *reinterpret_cast<float4*>(&w[0]) = *reinterpret_cast<const float4*>(&sW1[k * 128 + c0]);
                *reinterpret_cast<float4*>(&w[4]) = *reinterpret_cast<const float4*>(&sW1[k * 128 + c0 + 4]);
                #pragma unroll
                for (int j = 0; j < 8; ++j) acc[j] = fmaf(a, w[j], acc[j]);
            }
            float* hr = &sH[i16 * 132 + c0];
            #pragma unroll
            for (int j = 0; j < 8; ++j) hr[j] = fmaxf(acc[j], 0.f);
        }
        __syncthreads();

        // GEMM2: 16 nodes x 64 outs, 4 outs/thread, K=128
        {
            const int c0 = g16 * 4;
            float acc[4];
            #pragma unroll
            for (int j = 0; j < 4; ++j) acc[j] = sB2[c0 + j];
            const float* hr = &sH[i16 * 132];
            #pragma unroll 4
            for (int k = 0; k < 128; ++k) {
                const float a = hr[k];
                float4 w = *reinterpret_cast<const float4*>(&sW2[k * 64 + c0]);
                acc[0] = fmaf(a, w.x, acc[0]);
                acc[1] = fmaf(a, w.y, acc[1]);
                acc[2] = fmaf(a, w.z, acc[2]);
                acc[3] = fmaf(a, w.w, acc[3]);
            }
            float* yr = &sY[i16 * 68 + c0];
            #pragma unroll
            for (int j = 0; j < 4; ++j) yr[j] = acc[j];
        }
        __syncthreads();

        // LayerNorm + residual: warp handles 2 nodes
        #pragma unroll
        for (int q = 0; q < 2; ++q) {
            const int i = wid * 2 + q;
            const float v0 = sY[i * 68 + lid];
            const float v1 = sY[i * 68 + 32 + lid];
            float s  = v0 + v1;
            float sq = v0 * v0 + v1 * v1;
            #pragma unroll
            for (int off = 16; off; off >>= 1) {
                s  += __shfl_xor_sync(0xffffffffu, s,  off);
                sq += __shfl_xor_sync(0xffffffffu, sq, off);
            }
            const float mean = s * (1.f / 64.f);
            const float var  = sq * (1.f / 64.f) - mean * mean;
            const float rstd = rsqrtf(var + LN_EPS);
            const size_t n = (size_t)(n0 + i);
            out[n * 64 + lid]      = sX[i * 132 + lid]      + (v0 - mean) * rstd * sS[lid]      + sO[lid];
            out[n * 64 + 32 + lid] = sX[i * 132 + 32 + lid] + (v1 - mean) * rstd * sS[32 + lid] + sO[32 + lid];
        }
    }
}

// =====================================================================
extern "C" void kernel_launch(void* const* d_in, const int* in_sizes, int n_in,
                              void* d_out, int out_size) {
    (void)in_sizes; (void)n_in; (void)out_size;
    const float* nodes     = (const float*)d_in[0];
    const float* edges     = (const float*)d_in[1];
    const int*   senders   = (const int*)d_in[2];
    const int*   receivers = (const int*)d_in[3];
    const float* msg_W1    = (const float*)d_in[4];
    const float* msg_b1    = (const float*)d_in[5];
    const float* msg_W2    = (const float*)d_in[6];
    const float* msg_b2    = (const float*)d_in[7];
    const float* node_W1   = (const float*)d_in[8];
    const float* node_b1   = (const float*)d_in[9];
    const float* node_W2   = (const float*)d_in[10];
    const float* node_b2   = (const float*)d_in[11];
    const float* ln_scale  = (const float*)d_in[12];
    const float* ln_offset = (const float*)d_in[13];
    float* out = (float*)d_out;

    static bool attr_done = false;
    if (!attr_done) {
        cudaFuncSetAttribute(proj_kernel, cudaFuncAttributeMaxDynamicSharedMemorySize, (128 * 128 + 128) * 4);
        cudaFuncSetAttribute(edge_kernel, cudaFuncAttributeMaxDynamicSharedMemorySize, EDGE_SMEM);
        cudaFuncSetAttribute(node_kernel, cudaFuncAttributeMaxDynamicSharedMemorySize, NODE_SMEM);
        attr_done = true;
    }

    zero_agg_kernel<<<256, 256>>>();
    proj_kernel<<<444, 256, (128 * 128 + 128) * 4>>>(nodes, msg_W1, msg_b1);
    edge_kernel<<<296, 256, EDGE_SMEM>>>(edges, senders, receivers, msg_W1, msg_W2, msg_b2);
    node_kernel<<<148, 256, NODE_SMEM>>>(nodes, node_W1, node_b1, node_W2, node_b2,
                                         ln_scale, ln_offset, out);
}

// round 5
// speedup vs baseline: 1.0044x; 1.0016x over previous
#include <cuda_runtime.h>

// ---------------- fixed problem shapes ----------------
#define N_NODES 100000
#define D 64
#define E_EDGES 1600000
#define MSG_H 128
#define MSG_OUT 64
#define NODE_H 128
#define LN_EPS 1e-5f

// ---------------- device scratch (allowed: __device__ globals) ----------
__device__ __align__(16) float g_Ps[(size_t)N_NODES * 128];  // nodes @ W1[0:64,:]
__device__ __align__(16) float g_Pr[(size_t)N_NODES * 128];  // nodes @ W1[64:128,:] + b1
__device__ __align__(16) float g_agg[(size_t)N_NODES * 64];  // segment-sum of messages

// =====================================================================
// Kernel 0: zero aggregation buffer
// =====================================================================
__global__ void zero_agg_kernel() {
    float4* p = reinterpret_cast<float4*>(g_agg);
    const int n4 = N_NODES * 64 / 4;
    for (int i = blockIdx.x * blockDim.x + threadIdx.x; i < n4; i += gridDim.x * blockDim.x)
        p[i] = make_float4(0.f, 0.f, 0.f, 0.f);
}

// =====================================================================
// Kernel 1: node projections. 256 threads, 2 nodes per iteration.
//   thread t: node = n0 + (t>>7), col c = t&127; computes Ps and Pr.
// =====================================================================
__global__ __launch_bounds__(256, 3)
void proj_kernel(const float* __restrict__ nodes,
                 const float* __restrict__ msg_W1,
                 const float* __restrict__ msg_b1)
{
    extern __shared__ float sm[];
    float* sW = sm;              // [128][128]: rows 0..63 sender dims, 64..127 receiver dims
    float* sN = sm + 128 * 128;  // [2][64] node rows

    const int tid = threadIdx.x;
    for (int i = tid; i < 128 * 128; i += 256) sW[i] = msg_W1[i];
    __syncthreads();

    const int sub = tid >> 7;      // which of the 2 nodes
    const int c   = tid & 127;     // output column
    const float bias = msg_b1[c];

    const int numPairs = N_NODES / 2;
    for (int p = blockIdx.x; p < numPairs; p += gridDim.x) {
        const int n0 = p * 2;
        if (tid < 128) sN[tid] = nodes[(size_t)n0 * 64 + tid];
        __syncthreads();

        float as = 0.f, ar = 0.f;
        const float* nr = &sN[sub * 64];
        #pragma unroll 8
        for (int k = 0; k < 64; ++k) {
            const float a = nr[k];
            as = fmaf(a, sW[k * 128 + c], as);
            ar = fmaf(a, sW[(64 + k) * 128 + c], ar);
        }
        const int n = n0 + sub;
        g_Ps[(size_t)n * 128 + c] = as;
        g_Pr[(size_t)n * 128 + c] = ar + bias;
        __syncthreads();
    }
}

// =====================================================================
// Kernel 2: edge message MLP + scatter-add. 64-edge tiles, 256 threads,
// 2 edges per thread (pair), persistent grid-stride. Smem: 115.2KB -> 2 CTA/SM.
//   h   = relu(Ps[s] + Pr[r] + edges @ W1_edge)   [64 x 128]
//   msg = relu(h @ W2 + b2)                       [64 x 64]
//   agg[r] += msg   (atomicAdd -> REDG)
// =====================================================================
#define ES_W1   (64 * 128)
#define ES_W2   (128 * 64)
#define ES_E    (64 * 64)
#define ES_H    (64 * 130)
#define EDGE_SMEM ((ES_W1 + ES_W2 + ES_E + ES_H) * 4)

__global__ __launch_bounds__(256, 2)
void edge_kernel(const float* __restrict__ edges,
                 const int* __restrict__ senders,
                 const int* __restrict__ receivers,
                 const float* __restrict__ msg_W1,
                 const float* __restrict__ msg_W2,
                 const float* __restrict__ msg_b2)
{
    extern __shared__ float sm[];
    float* sW1 = sm;               // [64][128]  (W1 rows 128..191: edge-feature part)
    float* sW2 = sW1 + ES_W1;      // [128][64]
    float* sE  = sW2 + ES_W2;      // [64][64], XOR-swizzled rows
    float* sH  = sE  + ES_E;       // [64][130]

    const int tid = threadIdx.x;
    for (int i = tid; i < ES_W1; i += 256)
        sW1[i] = msg_W1[(128 + (i >> 7)) * 128 + (i & 127)];
    for (int i = tid; i < ES_W2; i += 256)
        sW2[i] = msg_W2[i];

    const int pair = tid >> 3;          // 0..31  (handles edges 2*pair, 2*pair+1)
    const int sub  = tid & 7;           // 0..7
    const int c0   = sub * 16;          // GEMM1 column base
    const int o0   = sub * 8;           // GEMM2 output base
    const int swz  = (pair & 3) * 8;    // edge-tile bank swizzle (floats)

    float rb2[8];
    #pragma unroll
    for (int j = 0; j < 8; ++j) rb2[j] = __ldg(&msg_b2[o0 + j]);

    const int numTiles = E_EDGES / 64;
    for (int tile = blockIdx.x; tile < numTiles; tile += gridDim.x) {
        const int e0 = tile * 64;
        __syncthreads();   // previous iteration's smem reads complete
        // ---- load edge tile (64x64 floats = 1024 float4), XOR-swizzled ----
        #pragma unroll
        for (int i = 0; i < 4; ++i) {
            const int idx = tid + i * 256;        // float4 index in tile
            const int row = idx >> 4;
            const int c4  = idx & 15;
            reinterpret_cast<float4*>(sE)[row * 16 + (c4 ^ (row & 6))] =
                reinterpret_cast<const float4*>(edges)[(size_t)e0 * 16 + idx];
        }
        const int eA = e0 + 2 * pair;
        const int s0 = __ldg(&senders[eA]);
        const int s1 = __ldg(&senders[eA + 1]);
        const int r0 = __ldg(&receivers[eA]);
        const int r1 = __ldg(&receivers[eA + 1]);
        __syncthreads();

        // ---- GEMM1: 2 edges x 16 cols, K=64; acc init = Ps[s] + Pr[r] ----
        float acc0[16], acc1[16];
        {
            const float4* ps0 = reinterpret_cast<const float4*>(&g_Ps[(size_t)s0 * 128 + c0]);
            const float4* pr0 = reinterpret_cast<const float4*>(&g_Pr[(size_t)r0 * 128 + c0]);
            const float4* ps1 = reinterpret_cast<const float4*>(&g_Ps[(size_t)s1 * 128 + c0]);
            const float4* pr1 = reinterpret_cast<const float4*>(&g_Pr[(size_t)r1 * 128 + c0]);
            #pragma unroll
            for (int q = 0; q < 4; ++q) {
                float4 a = ps0[q], b = pr0[q];
                acc0[q*4+0]=a.x+b.x; acc0[q*4+1]=a.y+b.y; acc0[q*4+2]=a.z+b.z; acc0[q*4+3]=a.w+b.w;
                float4 cc = ps1[q], d = pr1[q];
                acc1[q*4+0]=cc.x+d.x; acc1[q*4+1]=cc.y+d.y; acc1[q*4+2]=cc.z+d.z; acc1[q*4+3]=cc.w+d.w;
            }
        }
        const float* er0 = &sE[(2 * pair) * 64];
        const float* er1 = &sE[(2 * pair + 1) * 64];
        #pragma unroll 4
        for (int k = 0; k < 64; ++k) {
            const float a0 = er0[k ^ swz];
            const float a1 = er1[k ^ swz];
            float w[16];
            const float* wr = &sW1[k * 128 + c0];
            *reinterpret_cast<float4*>(&w[0])  = *reinterpret_cast<const float4*>(wr);
            *reinterpret_cast<float4*>(&w[4])  = *reinterpret_cast<const float4*>(wr + 4);
            *reinterpret_cast<float4*>(&w[8])  = *reinterpret_cast<const float4*>(wr + 8);
            *reinterpret_cast<float4*>(&w[12]) = *reinterpret_cast<const float4*>(wr + 12);
            #pragma unroll
            for (int j = 0; j < 16; ++j) {
                acc0[j] = fmaf(a0, w[j], acc0[j]);
                acc1[j] = fmaf(a1, w[j], acc1[j]);
            }
        }
        // ---- ReLU, store h ----
        {
            float* h0 = &sH[(2 * pair) * 130 + c0];
            float* h1 = &sH[(2 * pair + 1) * 130 + c0];
            #pragma unroll
            for (int j = 0; j < 16; ++j) {
                h0[j] = fmaxf(acc0[j], 0.f);
                h1[j] = fmaxf(acc1[j], 0.f);
            }
        }
        __syncthreads();

        // ---- GEMM2: 2 edges x 8 outs, K=128 ----
        float m0[8], m1[8];
        #pragma unroll
        for (int j = 0; j < 8; ++j) { m0[j] = rb2[j]; m1[j] = rb2[j]; }
        const float* h0 = &sH[(2 * pair) * 130];
        const float* h1 = &sH[(2 * pair + 1) * 130];
        #pragma unroll 4
        for (int k = 0; k < 128; ++k) {
            const float a0 = h0[k];
            const float a1 = h1[k];
            float w[8];
            *reinterpret_cast<float4*>(&w[0]) = *reinterpret_cast<const float4*>(&sW2[k * 64 + o0]);
            *reinterpret_cast<float4*>(&w[4]) = *reinterpret_cast<const float4*>(&sW2[k * 64 + o0 + 4]);
            #pragma unroll
            for (int j = 0; j < 8; ++j) {
                m0[j] = fmaf(a0, w[j], m0[j]);
                m1[j] = fmaf(a1, w[j], m1[j]);
            }
        }
        // ---- ReLU + scatter-add ----
        float* d0 = &g_agg[(size_t)r0 * 64 + o0];
        float* d1 = &g_agg[(size_t)r1 * 64 + o0];
        #pragma unroll
        for (int j = 0; j < 8; ++j) atomicAdd(&d0[j], fmaxf(m0[j], 0.f));
        #pragma unroll
        for (int j = 0; j < 8; ++j) atomicAdd(&d1[j], fmaxf(m1[j], 0.f));
    }
}

// =====================================================================
// Kernel 3: node update MLP + LayerNorm + residual. 16-node tiles,
// 256 threads, persistent 148 blocks. Smem ~120.8KB -> 1 CTA/SM.
// =====================================================================
#define NS_W1 (128 * 128)
#define NS_W2 (128 * 64)
#define NS_X  (16 * 132)
#define NS_H  (16 * 132)
#define NS_Y  (16 * 68)
#define NODE_SMEM ((NS_W1 + NS_W2 + 128 + 64 + 64 + 64 + NS_X + NS_H + NS_Y) * 4)

__global__ __launch_bounds__(256, 1)
void node_kernel(const float* __restrict__ nodes,
                 const float* __restrict__ node_W1,
                 const float* __restrict__ node_b1,
                 const float* __restrict__ node_W2,
                 const float* __restrict__ node_b2,
                 const float* __restrict__ ln_scale,
                 const float* __restrict__ ln_offset,
                 float* __restrict__ out)
{
    extern __shared__ float sm[];
    float* sW1 = sm;               // [128][128]
    float* sW2 = sW1 + NS_W1;      // [128][64]
    float* sB1 = sW2 + NS_W2;      // [128]
    float* sB2 = sB1 + 128;        // [64]
    float* sS  = sB2 + 64;         // [64]
    float* sO  = sS + 64;          // [64]
    float* sX  = sO + 64;          // [16][132]
    float* sH  = sX + NS_X;        // [16][132]
    float* sY  = sH + NS_H;        // [16][68]

    const int tid = threadIdx.x;
    for (int i = tid; i < NS_W1; i += 256) sW1[i] = node_W1[i];
    for (int i = tid; i < NS_W2; i += 256) sW2[i] = node_W2[i];
    if (tid < 128) sB1[tid] = node_b1[tid];
    if (tid < 64) { sB2[tid] = node_b2[tid]; sS[tid] = ln_scale[tid]; sO[tid] = ln_offset[tid]; }

    const int i16 = tid >> 4;   // node within tile (GEMM mapping)
    const int g16 = tid & 15;
    const int wid = tid >> 5, lid = tid & 31;
    const int numTiles = N_NODES / 16;

    for (int tile = blockIdx.x; tile < numTiles; tile += gridDim.x) {
        const int n0 = tile * 16;
        __syncthreads();
        for (int idx = tid; idx < 16 * 128; idx += 256) {
            const int i = idx >> 7, c = idx & 127;
            sX[i * 132 + c] = (c < 64) ? nodes[(size_t)(n0 + i) * 64 + c]
                                       : g_agg[(size_t)(n0 + i) * 64 + (c - 64)];
        }
        __syncthreads();

        // GEMM1: 16 nodes x 128 cols, 8 cols/thread, K=128
        {
            const int c0 = g16 * 8;
            float acc[8];
            #pragma unroll
            for (int j = 0; j < 8; ++j) acc[j] = sB1[c0 + j];
            const float* xr = &sX[i16 * 132];
            #pragma unroll 4
            for (int k = 0; k < 128; ++k) {
                const float a = xr[k];
                float w[8];
                *reinterpret_cast<float4*>(&w[0]) = *reinterpret_cast<const float4*>(&sW1[k * 128 + c0]);
                *reinterpret_cast<float4*>(&w[4]) = *reinterpret_cast<const float4*>(&sW1[k * 128 + c0 + 4]);
                #pragma unroll
                for (int j = 0; j < 8; ++j) acc[j] = fmaf(a, w[j], acc[j]);
            }
            float* hr = &sH[i16 * 132 + c0];
            #pragma unroll
            for (int j = 0; j < 8; ++j) hr[j] = fmaxf(acc[j], 0.f);
        }
        __syncthreads();

        // GEMM2: 16 nodes x 64 outs, 4 outs/thread, K=128
        {
            const int c0 = g16 * 4;
            float acc[4];
            #pragma unroll
            for (int j = 0; j < 4; ++j) acc[j] = sB2[c0 + j];
            const float* hr = &sH[i16 * 132];
            #pragma unroll 4
            for (int k = 0; k < 128; ++k) {
                const float a = hr[k];
                float4 w = *reinterpret_cast<const float4*>(&sW2[k * 64 + c0]);
                acc[0] = fmaf(a, w.x, acc[0]);
                acc[1] = fmaf(a, w.y, acc[1]);
                acc[2] = fmaf(a, w.z, acc[2]);
                acc[3] = fmaf(a, w.w, acc[3]);
            }
            float* yr = &sY[i16 * 68 + c0];
            #pragma unroll
            for (int j = 0; j < 4; ++j) yr[j] = acc[j];
        }
        __syncthreads();

        // LayerNorm + residual: warp handles 2 nodes
        #pragma unroll
        for (int q = 0; q < 2; ++q) {
            const int i = wid * 2 + q;
            const float v0 = sY[i * 68 + lid];
            const float v1 = sY[i * 68 + 32 + lid];
            float s  = v0 + v1;
            float sq = v0 * v0 + v1 * v1;
            #pragma unroll
            for (int off = 16; off; off >>= 1) {
                s  += __shfl_xor_sync(0xffffffffu, s,  off);
                sq += __shfl_xor_sync(0xffffffffu, sq, off);
            }
            const float mean = s * (1.f / 64.f);
            const float var  = sq * (1.f / 64.f) - mean * mean;
            const float rstd = rsqrtf(var + LN_EPS);
            const size_t n = (size_t)(n0 + i);
            out[n * 64 + lid]      = sX[i * 132 + lid]      + (v0 - mean) * rstd * sS[lid]      + sO[lid];
            out[n * 64 + 32 + lid] = sX[i * 132 + 32 + lid] + (v1 - mean) * rstd * sS[32 + lid] + sO[32 + lid];
        }
    }
}

// =====================================================================
extern "C" void kernel_launch(void* const* d_in, const int* in_sizes, int n_in,
                              void* d_out, int out_size) {
    (void)in_sizes; (void)n_in; (void)out_size;
    const float* nodes     = (const float*)d_in[0];
    const float* edges     = (const float*)d_in[1];
    const int*   senders   = (const int*)d_in[2];
    const int*   receivers = (const int*)d_in[3];
    const float* msg_W1    = (const float*)d_in[4];
    const float* msg_b1    = (const float*)d_in[5];
    const float* msg_W2    = (const float*)d_in[6];
    const float* msg_b2    = (const float*)d_in[7];
    const float* node_W1   = (const float*)d_in[8];
    const float* node_b1   = (const float*)d_in[9];
    const float* node_W2   = (const float*)d_in[10];
    const float* node_b2   = (const float*)d_in[11];
    const float* ln_scale  = (const float*)d_in[12];
    const float* ln_offset = (const float*)d_in[13];
    float* out = (float*)d_out;

    static bool attr_done = false;
    if (!attr_done) {
        cudaFuncSetAttribute(proj_kernel, cudaFuncAttributeMaxDynamicSharedMemorySize, (128 * 128 + 128) * 4);
        cudaFuncSetAttribute(edge_kernel, cudaFuncAttributeMaxDynamicSharedMemorySize, EDGE_SMEM);
        cudaFuncSetAttribute(node_kernel, cudaFuncAttributeMaxDynamicSharedMemorySize, NODE_SMEM);
        attr_done = true;
    }

    zero_agg_kernel<<<256, 256>>>();
    proj_kernel<<<444, 256, (128 * 128 + 128) * 4>>>(nodes, msg_W1, msg_b1);
    edge_kernel<<<296, 256, EDGE_SMEM>>>(edges, senders, receivers, msg_W1, msg_W2, msg_b2);
    node_kernel<<<148, 256, NODE_SMEM>>>(nodes, node_W1, node_b1, node_W2, node_b2,
                                         ln_scale, ln_offset, out);
}

// round 9
// speedup vs baseline: 3.3301x; 3.3155x over previous
#include <cuda_runtime.h>
#include <cuda_bf16.h>
#include <cstdint>

// ---------------- fixed problem shapes ----------------
#define N_NODES 100000
#define D 64
#define E_EDGES 1600000
#define MSG_H 128
#define MSG_OUT 64
#define NODE_H 128
#define LN_EPS 1e-5f

// ---------------- device scratch ----------------
__device__ __align__(16) float g_Ps[(size_t)N_NODES * 128];  // nodes @ W1[0:64,:]
__device__ __align__(16) float g_Pr[(size_t)N_NODES * 128];  // nodes @ W1[64:128,:] + b1
__device__ __align__(16) float g_agg[(size_t)N_NODES * 64];  // segment-sum of messages

// =====================================================================
// warp-MMA helpers (sm_80 baseline features -> compile for compute_103)
// =====================================================================
__device__ __forceinline__ uint32_t smem_u32(const void* p) {
    uint32_t a;
    asm("{ .reg .u64 t; cvta.to.shared.u64 t, %1; cvt.u32.u64 %0, t; }" : "=r"(a) : "l"(p));
    return a;
}

__device__ __forceinline__ void ldmx4(uint32_t* r, uint32_t addr) {
    asm volatile("ldmatrix.sync.aligned.m8n8.x4.shared.b16 {%0,%1,%2,%3}, [%4];"
                 : "=r"(r[0]), "=r"(r[1]), "=r"(r[2]), "=r"(r[3]) : "r"(addr));
}

__device__ __forceinline__ void mma16816(float* d, const uint32_t* a, uint32_t b0, uint32_t b1) {
    asm volatile(
        "mma.sync.aligned.m16n8k16.row.col.f32.bf16.bf16.f32 "
        "{%0,%1,%2,%3}, {%4,%5,%6,%7}, {%8,%9}, {%0,%1,%2,%3};"
        : "+f"(d[0]), "+f"(d[1]), "+f"(d[2]), "+f"(d[3])
        : "r"(a[0]), "r"(a[1]), "r"(a[2]), "r"(a[3]), "r"(b0), "r"(b1));
}

__device__ __forceinline__ void bfsplit2(float x0, float x1, uint32_t& hi, uint32_t& lo) {
    __nv_bfloat162 h = __floats2bfloat162_rn(x0, x1);
    float r0 = x0 - __low2float(h);
    float r1 = x1 - __high2float(h);
    __nv_bfloat162 l = __floats2bfloat162_rn(r0, r1);
    hi = reinterpret_cast<uint32_t&>(h);
    lo = reinterpret_cast<uint32_t&>(l);
}

// =====================================================================
// Kernel 0: zero aggregation buffer
// =====================================================================
__global__ void zero_agg_kernel() {
    float4* p = reinterpret_cast<float4*>(g_agg);
    const int n4 = N_NODES * 64 / 4;
    for (int i = blockIdx.x * blockDim.x + threadIdx.x; i < n4; i += gridDim.x * blockDim.x)
        p[i] = make_float4(0.f, 0.f, 0.f, 0.f);
}

// =====================================================================
// Kernel 1: node projections (fp32 FFMA; 3.3 GFLOP total)
// =====================================================================
__global__ __launch_bounds__(256, 3)
void proj_kernel(const float* __restrict__ nodes,
                 const float* __restrict__ msg_W1,
                 const float* __restrict__ msg_b1)
{
    extern __shared__ float sm[];
    float* sW = sm;
    float* sN = sm + 128 * 128;

    const int tid = threadIdx.x;
    for (int i = tid; i < 128 * 128; i += 256) sW[i] = msg_W1[i];
    __syncthreads();

    const int sub = tid >> 7;
    const int c   = tid & 127;
    const float bias = msg_b1[c];

    const int numPairs = N_NODES / 2;
    for (int p = blockIdx.x; p < numPairs; p += gridDim.x) {
        const int n0 = p * 2;
        if (tid < 128) sN[tid] = nodes[(size_t)n0 * 64 + tid];
        __syncthreads();
        float as = 0.f, ar = 0.f;
        const float* nr = &sN[sub * 64];
        #pragma unroll 8
        for (int k = 0; k < 64; ++k) {
            const float a = nr[k];
            as = fmaf(a, sW[k * 128 + c], as);
            ar = fmaf(a, sW[(64 + k) * 128 + c], ar);
        }
        const int n = n0 + sub;
        g_Ps[(size_t)n * 128 + c] = as;
        g_Pr[(size_t)n * 128 + c] = ar + bias;
        __syncthreads();
    }
}

// =====================================================================
// Kernel 2: edge message MLP via warp-level bf16-split mma.sync.
// 128-edge tiles, 256 threads (8 warps), persistent.
//   GEMM1: D1[128x128] = Ps[s]+Pr[r] (acc init) + E[128x64] @ W1e[64x128]
//   h = relu(D1) -> bf16 hi/lo in smem
//   GEMM2: D2[128x64] = h @ W2;  msg = relu(D2 + b2);  agg[r] += msg
// =====================================================================
#define OFF_B2   0
#define OFF_SID  256
#define OFF_RID  768
#define OFF_AH   1280
#define OFF_AL   (OFF_AH  + 18432)
#define OFF_W1H  (OFF_AL  + 18432)
#define OFF_W1L  (OFF_W1H + 18432)
#define OFF_W2H  (OFF_W1L + 18432)
#define OFF_W2L  (OFF_W2H + 17408)
#define OFF_HH   (OFF_W2L + 17408)
#define OFF_HL   (OFF_HH  + 34816)
#define EDGE_SMEM_BYTES (OFF_HL + 34816)   // 179456 bytes

// element strides (bf16): A rows 72 (144B), W1T rows 72, h/W2T rows 136 (272B)

__global__ __launch_bounds__(256, 1)
void edge_kernel(const float* __restrict__ edges,
                 const int* __restrict__ senders,
                 const int* __restrict__ receivers,
                 const float* __restrict__ msg_W1,
                 const float* __restrict__ msg_W2,
                 const float* __restrict__ msg_b2)
{
    extern __shared__ char smc[];
    const uint32_t sb = smem_u32(smc);
    const int tid  = threadIdx.x;
    const int warp = tid >> 5;
    const int lane = tid & 31;
    const int g    = lane >> 2;       // groupID
    const int tg   = lane & 3;        // threadID-in-group
    const int qq   = lane >> 3;       // ldmatrix quadrant
    const int lr   = lane & 7;        // row within quadrant

    int* sSid = reinterpret_cast<int*>(smc + OFF_SID);
    int* sRid = reinterpret_cast<int*>(smc + OFF_RID);
    float* sB2 = reinterpret_cast<float*>(smc + OFF_B2);

    if (tid < 64) sB2[tid] = msg_b2[tid];

    // ---- stage W1e^T as [n=128][k=64] bf16 hi/lo, stride 72 ----
    for (int i = tid; i < 128 * 64; i += 256) {
        const int n = i >> 6, k = i & 63;
        const float w = msg_W1[(128 + k) * 128 + n];
        const __nv_bfloat16 h = __float2bfloat16_rn(w);
        const __nv_bfloat16 l = __float2bfloat16_rn(w - __bfloat162float(h));
        *reinterpret_cast<__nv_bfloat16*>(smc + OFF_W1H + (n * 72 + k) * 2) = h;
        *reinterpret_cast<__nv_bfloat16*>(smc + OFF_W1L + (n * 72 + k) * 2) = l;
    }
    // ---- stage W2^T as [n=64][k=128] bf16 hi/lo, stride 136 ----
    for (int i = tid; i < 64 * 128; i += 256) {
        const int n = i >> 7, k = i & 127;
        const float w = msg_W2[k * 64 + n];
        const __nv_bfloat16 h = __float2bfloat16_rn(w);
        const __nv_bfloat16 l = __float2bfloat16_rn(w - __bfloat162float(h));
        *reinterpret_cast<__nv_bfloat16*>(smc + OFF_W2H + (n * 136 + k) * 2) = h;
        *reinterpret_cast<__nv_bfloat16*>(smc + OFF_W2L + (n * 136 + k) * 2) = l;
    }

    const int nbase = warp * 16;   // GEMM1 n-strip
    const int ncol0 = warp * 8;    // GEMM2 n-strip

    const int numTiles = E_EDGES / 128;  // 12500
    for (int tile = blockIdx.x; tile < numTiles; tile += gridDim.x) {
        const int e0 = tile * 128;
        __syncthreads();  // prior tile's reads of A/h/ids complete

        // ---- stage edge tile [128][64] -> bf16 hi/lo (stride 72) ----
        #pragma unroll
        for (int cch = 0; cch < 2; ++cch) {
            const int c = tid + cch * 256;            // 0..511
            const int row = c >> 2, q = c & 3;        // q: 16-float chunk
            const float4* src = reinterpret_cast<const float4*>(
                &edges[(size_t)(e0 + row) * 64 + q * 16]);
            uint32_t hi[8], lo[8];
            #pragma unroll
            for (int j = 0; j < 4; ++j) {
                const float4 f = src[j];
                bfsplit2(f.x, f.y, hi[2 * j],     lo[2 * j]);
                bfsplit2(f.z, f.w, hi[2 * j + 1], lo[2 * j + 1]);
            }
            char* dh = smc + OFF_AH + row * 144 + q * 32;
            char* dl = smc + OFF_AL + row * 144 + q * 32;
            *reinterpret_cast<uint4*>(dh)      = make_uint4(hi[0], hi[1], hi[2], hi[3]);
            *reinterpret_cast<uint4*>(dh + 16) = make_uint4(hi[4], hi[5], hi[6], hi[7]);
            *reinterpret_cast<uint4*>(dl)      = make_uint4(lo[0], lo[1], lo[2], lo[3]);
            *reinterpret_cast<uint4*>(dl + 16) = make_uint4(lo[4], lo[5], lo[6], lo[7]);
        }
        // ---- stage sender/receiver ids ----
        if (tid < 128) sSid[tid] = senders[e0 + tid];
        else           sRid[tid - 128] = receivers[e0 + tid - 128];
        __syncthreads();

        // ================= GEMM1 =================
        // acc init: Ps[s] + Pr[r] gathers (float2 per reg pair)
        float acc[8][2][4];
        #pragma unroll
        for (int mt = 0; mt < 8; ++mt) {
            const int er0 = mt * 16 + g, er1 = er0 + 8;
            const int s0 = sSid[er0], r0 = sRid[er0];
            const int s1 = sSid[er1], r1 = sRid[er1];
            #pragma unroll
            for (int nt = 0; nt < 2; ++nt) {
                const int n = nbase + nt * 8 + tg * 2;
                const float2 a0 = *reinterpret_cast<const float2*>(&g_Ps[(size_t)s0 * 128 + n]);
                const float2 b0 = *reinterpret_cast<const float2*>(&g_Pr[(size_t)r0 * 128 + n]);
                const float2 a1 = *reinterpret_cast<const float2*>(&g_Ps[(size_t)s1 * 128 + n]);
                const float2 b1 = *reinterpret_cast<const float2*>(&g_Pr[(size_t)r1 * 128 + n]);
                acc[mt][nt][0] = a0.x + b0.x;
                acc[mt][nt][1] = a0.y + b0.y;
                acc[mt][nt][2] = a1.x + b1.x;
                acc[mt][nt][3] = a1.y + b1.y;
            }
        }
        // K loop (K=64, 4 ksteps of 16)
        #pragma unroll
        for (int kt = 0; kt < 4; ++kt) {
            const int k0 = kt * 16;
            // B fragments: col = nbase + nt*8 + g, rows k0+tg*2 (+8)
            uint32_t bh[2][2], bl[2][2];
            #pragma unroll
            for (int nt = 0; nt < 2; ++nt) {
                const uint32_t bo = (uint32_t)(((nbase + nt * 8 + g) * 72 + k0 + tg * 2) * 2);
                bh[nt][0] = *reinterpret_cast<const uint32_t*>(smc + OFF_W1H + bo);
                bh[nt][1] = *reinterpret_cast<const uint32_t*>(smc + OFF_W1H + bo + 16);
                bl[nt][0] = *reinterpret_cast<const uint32_t*>(smc + OFF_W1L + bo);
                bl[nt][1] = *reinterpret_cast<const uint32_t*>(smc + OFF_W1L + bo + 16);
            }
            #pragma unroll
            for (int mt = 0; mt < 8; ++mt) {
                const uint32_t ao = (uint32_t)(((mt * 16 + (qq & 1) * 8 + lr) * 72
                                                + k0 + (qq >> 1) * 8) * 2);
                uint32_t Ah[4], Al[4];
                ldmx4(Ah, sb + OFF_AH + ao);
                ldmx4(Al, sb + OFF_AL + ao);
                #pragma unroll
                for (int nt = 0; nt < 2; ++nt) {
                    mma16816(acc[mt][nt], Ah, bh[nt][0], bh[nt][1]);
                    mma16816(acc[mt][nt], Ah, bl[nt][0], bl[nt][1]);
                    mma16816(acc[mt][nt], Al, bh[nt][0], bh[nt][1]);
                }
            }
        }
        // epilogue1: relu -> bf16 hi/lo h tile (stride 136 elems = 272 B)
        // NOTE: column n lives at byte offset n*2 (bf16), NOT n*4.
        #pragma unroll
        for (int mt = 0; mt < 8; ++mt) {
            const int er0 = mt * 16 + g, er1 = er0 + 8;
            #pragma unroll
            for (int nt = 0; nt < 2; ++nt) {
                const int n = nbase + nt * 8 + tg * 2;
                uint32_t hw, lw;
                bfsplit2(fmaxf(acc[mt][nt][0], 0.f), fmaxf(acc[mt][nt][1], 0.f), hw, lw);
                *reinterpret_cast<uint32_t*>(smc + OFF_HH + er0 * 272 + n * 2) = hw;
                *reinterpret_cast<uint32_t*>(smc + OFF_HL + er0 * 272 + n * 2) = lw;
                bfsplit2(fmaxf(acc[mt][nt][2], 0.f), fmaxf(acc[mt][nt][3], 0.f), hw, lw);
                *reinterpret_cast<uint32_t*>(smc + OFF_HH + er1 * 272 + n * 2) = hw;
                *reinterpret_cast<uint32_t*>(smc + OFF_HL + er1 * 272 + n * 2) = lw;
            }
        }
        __syncthreads();

        // ================= GEMM2 ================= (M=128, N=64, K=128)
        float acc2[8][4];
        #pragma unroll
        for (int mt = 0; mt < 8; ++mt)
            #pragma unroll
            for (int j = 0; j < 4; ++j) acc2[mt][j] = 0.f;

        #pragma unroll
        for (int kt = 0; kt < 8; ++kt) {
            const int k0 = kt * 16;
            const uint32_t bo = (uint32_t)(((ncol0 + g) * 136 + k0 + tg * 2) * 2);
            const uint32_t bh0 = *reinterpret_cast<const uint32_t*>(smc + OFF_W2H + bo);
            const uint32_t bh1 = *reinterpret_cast<const uint32_t*>(smc + OFF_W2H + bo + 16);
            const uint32_t bl0 = *reinterpret_cast<const uint32_t*>(smc + OFF_W2L + bo);
            const uint32_t bl1 = *reinterpret_cast<const uint32_t*>(smc + OFF_W2L + bo + 16);
            #pragma unroll
            for (int mt = 0; mt < 8; ++mt) {
                const uint32_t ao = (uint32_t)(((mt * 16 + (qq & 1) * 8 + lr) * 136
                                                + k0 + (qq >> 1) * 8) * 2);
                uint32_t Ah[4], Al[4];
                ldmx4(Ah, sb + OFF_HH + ao);
                ldmx4(Al, sb + OFF_HL + ao);
                mma16816(acc2[mt], Ah, bh0, bh1);
                mma16816(acc2[mt], Ah, bl0, bl1);
                mma16816(acc2[mt], Al, bh0, bh1);
            }
        }
        // epilogue2: + b2, relu, scatter-add
        {
            const int n = ncol0 + tg * 2;
            const float b0 = sB2[n], b1 = sB2[n + 1];
            #pragma unroll
            for (int mt = 0; mt < 8; ++mt) {
                const int er0 = mt * 16 + g, er1 = er0 + 8;
                const int r0 = sRid[er0], r1 = sRid[er1];
                atomicAdd(&g_agg[(size_t)r0 * 64 + n],     fmaxf(acc2[mt][0] + b0, 0.f));
                atomicAdd(&g_agg[(size_t)r0 * 64 + n + 1], fmaxf(acc2[mt][1] + b1, 0.f));
                atomicAdd(&g_agg[(size_t)r1 * 64 + n],     fmaxf(acc2[mt][2] + b0, 0.f));
                atomicAdd(&g_agg[(size_t)r1 * 64 + n + 1], fmaxf(acc2[mt][3] + b1, 0.f));
            }
        }
    }
}

// =====================================================================
// Kernel 3: node update MLP + LayerNorm + residual. 32-node tiles,
// 512 threads (16 warps), persistent 148 blocks.
// =====================================================================
#define NS_W1 (128 * 128)
#define NS_W2 (128 * 64)
#define NS_X  (32 * 132)
#define NS_H  (32 * 132)
#define NS_Y  (32 * 68)
#define NODE_SMEM ((NS_W1 + NS_W2 + 128 + 64 + 64 + 64 + NS_X + NS_H + NS_Y) * 4)

__global__ __launch_bounds__(512, 1)
void node_kernel(const float* __restrict__ nodes,
                 const float* __restrict__ node_W1,
                 const float* __restrict__ node_b1,
                 const float* __restrict__ node_W2,
                 const float* __restrict__ node_b2,
                 const float* __restrict__ ln_scale,
                 const float* __restrict__ ln_offset,
                 float* __restrict__ out)
{
    extern __shared__ float sm[];
    float* sW1 = sm;
    float* sW2 = sW1 + NS_W1;
    float* sB1 = sW2 + NS_W2;
    float* sB2 = sB1 + 128;
    float* sS  = sB2 + 64;
    float* sO  = sS + 64;
    float* sX  = sO + 64;
    float* sH  = sX + NS_X;
    float* sY  = sH + NS_H;

    const int tid = threadIdx.x;
    for (int i = tid; i < NS_W1; i += 512) sW1[i] = node_W1[i];
    for (int i = tid; i < NS_W2; i += 512) sW2[i] = node_W2[i];
    if (tid < 128) sB1[tid] = node_b1[tid];
    if (tid < 64) { sB2[tid] = node_b2[tid]; sS[tid] = ln_scale[tid]; sO[tid] = ln_offset[tid]; }

    const int ni  = tid >> 4;
    const int g16 = tid & 15;
    const int wid = tid >> 5, lid = tid & 31;
    const int numTiles = N_NODES / 32;

    for (int tile = blockIdx.x; tile < numTiles; tile += gridDim.x) {
        const int n0 = tile * 32;
        __syncthreads();
        for (int idx = tid; idx < 32 * 128; idx += 512) {
            const int i = idx >> 7, c = idx & 127;
            sX[i * 132 + c] = (c < 64) ? nodes[(size_t)(n0 + i) * 64 + c]
                                       : g_agg[(size_t)(n0 + i) * 64 + (c - 64)];
        }
        __syncthreads();

        {
            const int c0 = g16 * 8;
            float acc[8];
            #pragma unroll
            for (int j = 0; j < 8; ++j) acc[j] = sB1[c0 + j];
            const float* xr = &sX[ni * 132];
            #pragma unroll 4
            for (int k = 0; k < 128; ++k) {
                const float a = xr[k];
                float w[8];
                *reinterpret_cast<float4*>(&w[0]) = *reinterpret_cast<const float4*>(&sW1[k * 128 + c0]);
                *reinterpret_cast<float4*>(&w[4]) = *reinterpret_cast<const float4*>(&sW1[k * 128 + c0 + 4]);
                #pragma unroll
                for (int j = 0; j < 8; ++j) acc[j] = fmaf(a, w[j], acc[j]);
            }
            float* hr = &sH[ni * 132 + c0];
            #pragma unroll
            for (int j = 0; j < 8; ++j) hr[j] = fmaxf(acc[j], 0.f);
        }
        __syncthreads();

        {
            const int c0 = g16 * 4;
            float acc[4];
            #pragma unroll
            for (int j = 0; j < 4; ++j) acc[j] = sB2[c0 + j];
            const float* hr = &sH[ni * 132];
            #pragma unroll 4
            for (int k = 0; k < 128; ++k) {
                const float a = hr[k];
                const float4 w = *reinterpret_cast<const float4*>(&sW2[k * 64 + c0]);
                acc[0] = fmaf(a, w.x, acc[0]);
                acc[1] = fmaf(a, w.y, acc[1]);
                acc[2] = fmaf(a, w.z, acc[2]);
                acc[3] = fmaf(a, w.w, acc[3]);
            }
            float* yr = &sY[ni * 68 + c0];
            #pragma unroll
            for (int j = 0; j < 4; ++j) yr[j] = acc[j];
        }
        __syncthreads();

        #pragma unroll
        for (int q = 0; q < 2; ++q) {
            const int i = wid * 2 + q;
            const float v0 = sY[i * 68 + lid];
            const float v1 = sY[i * 68 + 32 + lid];
            float s  = v0 + v1;
            float sq = v0 * v0 + v1 * v1;
            #pragma unroll
            for (int off = 16; off; off >>= 1) {
                s  += __shfl_xor_sync(0xffffffffu, s,  off);
                sq += __shfl_xor_sync(0xffffffffu, sq, off);
            }
            const float mean = s * (1.f / 64.f);
            const float var  = sq * (1.f / 64.f) - mean * mean;
            const float rstd = rsqrtf(var + LN_EPS);
            const size_t n = (size_t)(n0 + i);
            out[n * 64 + lid]      = sX[i * 132 + lid]      + (v0 - mean) * rstd * sS[lid]      + sO[lid];
            out[n * 64 + 32 + lid] = sX[i * 132 + 32 + lid] + (v1 - mean) * rstd * sS[32 + lid] + sO[32 + lid];
        }
    }
}

// =====================================================================
extern "C" void kernel_launch(void* const* d_in, const int* in_sizes, int n_in,
                              void* d_out, int out_size) {
    (void)in_sizes; (void)n_in; (void)out_size;
    const float* nodes     = (const float*)d_in[0];
    const float* edges     = (const float*)d_in[1];
    const int*   senders   = (const int*)d_in[2];
    const int*   receivers = (const int*)d_in[3];
    const float* msg_W1    = (const float*)d_in[4];
    const float* msg_b1    = (const float*)d_in[5];
    const float* msg_W2    = (const float*)d_in[6];
    const float* msg_b2    = (const float*)d_in[7];
    const float* node_W1   = (const float*)d_in[8];
    const float* node_b1   = (const float*)d_in[9];
    const float* node_W2   = (const float*)d_in[10];
    const float* node_b2   = (const float*)d_in[11];
    const float* ln_scale  = (const float*)d_in[12];
    const float* ln_offset = (const float*)d_in[13];
    float* out = (float*)d_out;

    cudaFuncSetAttribute(proj_kernel, cudaFuncAttributeMaxDynamicSharedMemorySize, (128 * 128 + 128) * 4);
    cudaFuncSetAttribute(edge_kernel, cudaFuncAttributeMaxDynamicSharedMemorySize, EDGE_SMEM_BYTES);
    cudaFuncSetAttribute(node_kernel, cudaFuncAttributeMaxDynamicSharedMemorySize, NODE_SMEM);

    zero_agg_kernel<<<256, 256>>>();
    proj_kernel<<<444, 256, (128 * 128 + 128) * 4>>>(nodes, msg_W1, msg_b1);
    edge_kernel<<<148, 256, EDGE_SMEM_BYTES>>>(edges, senders, receivers, msg_W1, msg_W2, msg_b2);
    node_kernel<<<148, 512, NODE_SMEM>>>(nodes, node_W1, node_b1, node_W2, node_b2,
                                         ln_scale, ln_offset, out);
}

// round 10
// speedup vs baseline: 4.4185x; 1.3269x over previous
#include <cuda_runtime.h>
#include <cuda_bf16.h>
#include <cstdint>

// ---------------- fixed problem shapes ----------------
#define N_NODES 100000
#define D 64
#define E_EDGES 1600000
#define MSG_H 128
#define MSG_OUT 64
#define NODE_H 128
#define LN_EPS 1e-5f

// ---------------- device scratch ----------------
__device__ __align__(16) float g_Ps[(size_t)N_NODES * 128];  // nodes @ W1[0:64,:]
__device__ __align__(16) float g_Pr[(size_t)N_NODES * 128];  // nodes @ W1[64:128,:] + b1
__device__ __align__(16) float g_agg[(size_t)N_NODES * 64];  // segment-sum of messages

// =====================================================================
// warp-MMA helpers (sm_80 baseline features -> compile for compute_103)
// =====================================================================
__device__ __forceinline__ uint32_t smem_u32(const void* p) {
    uint32_t a;
    asm("{ .reg .u64 t; cvta.to.shared.u64 t, %1; cvt.u32.u64 %0, t; }" : "=r"(a) : "l"(p));
    return a;
}

__device__ __forceinline__ void ldmx4(uint32_t* r, uint32_t addr) {
    asm volatile("ldmatrix.sync.aligned.m8n8.x4.shared.b16 {%0,%1,%2,%3}, [%4];"
                 : "=r"(r[0]), "=r"(r[1]), "=r"(r[2]), "=r"(r[3]) : "r"(addr));
}

__device__ __forceinline__ void mma16816(float* d, const uint32_t* a, uint32_t b0, uint32_t b1) {
    asm volatile(
        "mma.sync.aligned.m16n8k16.row.col.f32.bf16.bf16.f32 "
        "{%0,%1,%2,%3}, {%4,%5,%6,%7}, {%8,%9}, {%0,%1,%2,%3};"
        : "+f"(d[0]), "+f"(d[1]), "+f"(d[2]), "+f"(d[3])
        : "r"(a[0]), "r"(a[1]), "r"(a[2]), "r"(a[3]), "r"(b0), "r"(b1));
}

__device__ __forceinline__ void bfsplit2(float x0, float x1, uint32_t& hi, uint32_t& lo) {
    __nv_bfloat162 h = __floats2bfloat162_rn(x0, x1);
    float r0 = x0 - __low2float(h);
    float r1 = x1 - __high2float(h);
    __nv_bfloat162 l = __floats2bfloat162_rn(r0, r1);
    hi = reinterpret_cast<uint32_t&>(h);
    lo = reinterpret_cast<uint32_t&>(l);
}

// =====================================================================
// Kernel 0: zero aggregation buffer
// =====================================================================
__global__ void zero_agg_kernel() {
    float4* p = reinterpret_cast<float4*>(g_agg);
    const int n4 = N_NODES * 64 / 4;
    for (int i = blockIdx.x * blockDim.x + threadIdx.x; i < n4; i += gridDim.x * blockDim.x)
        p[i] = make_float4(0.f, 0.f, 0.f, 0.f);
}

// =====================================================================
// Kernel 1: node projections (fp32 FFMA; 3.3 GFLOP total)
// =====================================================================
__global__ __launch_bounds__(256, 3)
void proj_kernel(const float* __restrict__ nodes,
                 const float* __restrict__ msg_W1,
                 const float* __restrict__ msg_b1)
{
    extern __shared__ float sm[];
    float* sW = sm;
    float* sN = sm + 128 * 128;

    const int tid = threadIdx.x;
    for (int i = tid; i < 128 * 128; i += 256) sW[i] = msg_W1[i];
    __syncthreads();

    const int sub = tid >> 7;
    const int c   = tid & 127;
    const float bias = msg_b1[c];

    const int numPairs = N_NODES / 2;
    for (int p = blockIdx.x; p < numPairs; p += gridDim.x) {
        const int n0 = p * 2;
        if (tid < 128) sN[tid] = nodes[(size_t)n0 * 64 + tid];
        __syncthreads();
        float as = 0.f, ar = 0.f;
        const float* nr = &sN[sub * 64];
        #pragma unroll 8
        for (int k = 0; k < 64; ++k) {
            const float a = nr[k];
            as = fmaf(a, sW[k * 128 + c], as);
            ar = fmaf(a, sW[(64 + k) * 128 + c], ar);
        }
        const int n = n0 + sub;
        g_Ps[(size_t)n * 128 + c] = as;
        g_Pr[(size_t)n * 128 + c] = ar + bias;
        __syncthreads();
    }
}

// =====================================================================
// Kernel 2: edge message MLP via warp-level bf16-split mma.sync.
// (unchanged from R9 — passed with rel_err 1.9e-6)
// =====================================================================
#define OFF_B2   0
#define OFF_SID  256
#define OFF_RID  768
#define OFF_AH   1280
#define OFF_AL   (OFF_AH  + 18432)
#define OFF_W1H  (OFF_AL  + 18432)
#define OFF_W1L  (OFF_W1H + 18432)
#define OFF_W2H  (OFF_W1L + 18432)
#define OFF_W2L  (OFF_W2H + 17408)
#define OFF_HH   (OFF_W2L + 17408)
#define OFF_HL   (OFF_HH  + 34816)
#define EDGE_SMEM_BYTES (OFF_HL + 34816)   // 179456 bytes

__global__ __launch_bounds__(256, 1)
void edge_kernel(const float* __restrict__ edges,
                 const int* __restrict__ senders,
                 const int* __restrict__ receivers,
                 const float* __restrict__ msg_W1,
                 const float* __restrict__ msg_W2,
                 const float* __restrict__ msg_b2)
{
    extern __shared__ char smc[];
    const uint32_t sb = smem_u32(smc);
    const int tid  = threadIdx.x;
    const int warp = tid >> 5;
    const int lane = tid & 31;
    const int g    = lane >> 2;
    const int tg   = lane & 3;
    const int qq   = lane >> 3;
    const int lr   = lane & 7;

    int* sSid = reinterpret_cast<int*>(smc + OFF_SID);
    int* sRid = reinterpret_cast<int*>(smc + OFF_RID);
    float* sB2 = reinterpret_cast<float*>(smc + OFF_B2);

    if (tid < 64) sB2[tid] = msg_b2[tid];

    for (int i = tid; i < 128 * 64; i += 256) {
        const int n = i >> 6, k = i & 63;
        const float w = msg_W1[(128 + k) * 128 + n];
        const __nv_bfloat16 h = __float2bfloat16_rn(w);
        const __nv_bfloat16 l = __float2bfloat16_rn(w - __bfloat162float(h));
        *reinterpret_cast<__nv_bfloat16*>(smc + OFF_W1H + (n * 72 + k) * 2) = h;
        *reinterpret_cast<__nv_bfloat16*>(smc + OFF_W1L + (n * 72 + k) * 2) = l;
    }
    for (int i = tid; i < 64 * 128; i += 256) {
        const int n = i >> 7, k = i & 127;
        const float w = msg_W2[k * 64 + n];
        const __nv_bfloat16 h = __float2bfloat16_rn(w);
        const __nv_bfloat16 l = __float2bfloat16_rn(w - __bfloat162float(h));
        *reinterpret_cast<__nv_bfloat16*>(smc + OFF_W2H + (n * 136 + k) * 2) = h;
        *reinterpret_cast<__nv_bfloat16*>(smc + OFF_W2L + (n * 136 + k) * 2) = l;
    }

    const int nbase = warp * 16;
    const int ncol0 = warp * 8;

    const int numTiles = E_EDGES / 128;
    for (int tile = blockIdx.x; tile < numTiles; tile += gridDim.x) {
        const int e0 = tile * 128;
        __syncthreads();

        #pragma unroll
        for (int cch = 0; cch < 2; ++cch) {
            const int c = tid + cch * 256;
            const int row = c >> 2, q = c & 3;
            const float4* src = reinterpret_cast<const float4*>(
                &edges[(size_t)(e0 + row) * 64 + q * 16]);
            uint32_t hi[8], lo[8];
            #pragma unroll
            for (int j = 0; j < 4; ++j) {
                const float4 f = src[j];
                bfsplit2(f.x, f.y, hi[2 * j],     lo[2 * j]);
                bfsplit2(f.z, f.w, hi[2 * j + 1], lo[2 * j + 1]);
            }
            char* dh = smc + OFF_AH + row * 144 + q * 32;
            char* dl = smc + OFF_AL + row * 144 + q * 32;
            *reinterpret_cast<uint4*>(dh)      = make_uint4(hi[0], hi[1], hi[2], hi[3]);
            *reinterpret_cast<uint4*>(dh + 16) = make_uint4(hi[4], hi[5], hi[6], hi[7]);
            *reinterpret_cast<uint4*>(dl)      = make_uint4(lo[0], lo[1], lo[2], lo[3]);
            *reinterpret_cast<uint4*>(dl + 16) = make_uint4(lo[4], lo[5], lo[6], lo[7]);
        }
        if (tid < 128) sSid[tid] = senders[e0 + tid];
        else           sRid[tid - 128] = receivers[e0 + tid - 128];
        __syncthreads();

        float acc[8][2][4];
        #pragma unroll
        for (int mt = 0; mt < 8; ++mt) {
            const int er0 = mt * 16 + g, er1 = er0 + 8;
            const int s0 = sSid[er0], r0 = sRid[er0];
            const int s1 = sSid[er1], r1 = sRid[er1];
            #pragma unroll
            for (int nt = 0; nt < 2; ++nt) {
                const int n = nbase + nt * 8 + tg * 2;
                const float2 a0 = *reinterpret_cast<const float2*>(&g_Ps[(size_t)s0 * 128 + n]);
                const float2 b0 = *reinterpret_cast<const float2*>(&g_Pr[(size_t)r0 * 128 + n]);
                const float2 a1 = *reinterpret_cast<const float2*>(&g_Ps[(size_t)s1 * 128 + n]);
                const float2 b1 = *reinterpret_cast<const float2*>(&g_Pr[(size_t)r1 * 128 + n]);
                acc[mt][nt][0] = a0.x + b0.x;
                acc[mt][nt][1] = a0.y + b0.y;
                acc[mt][nt][2] = a1.x + b1.x;
                acc[mt][nt][3] = a1.y + b1.y;
            }
        }
        #pragma unroll
        for (int kt = 0; kt < 4; ++kt) {
            const int k0 = kt * 16;
            uint32_t bh[2][2], bl[2][2];
            #pragma unroll
            for (int nt = 0; nt < 2; ++nt) {
                const uint32_t bo = (uint32_t)(((nbase + nt * 8 + g) * 72 + k0 + tg * 2) * 2);
                bh[nt][0] = *reinterpret_cast<const uint32_t*>(smc + OFF_W1H + bo);
                bh[nt][1] = *reinterpret_cast<const uint32_t*>(smc + OFF_W1H + bo + 16);
                bl[nt][0] = *reinterpret_cast<const uint32_t*>(smc + OFF_W1L + bo);
                bl[nt][1] = *reinterpret_cast<const uint32_t*>(smc + OFF_W1L + bo + 16);
            }
            #pragma unroll
            for (int mt = 0; mt < 8; ++mt) {
                const uint32_t ao = (uint32_t)(((mt * 16 + (qq & 1) * 8 + lr) * 72
                                                + k0 + (qq >> 1) * 8) * 2);
                uint32_t Ah[4], Al[4];
                ldmx4(Ah, sb + OFF_AH + ao);
                ldmx4(Al, sb + OFF_AL + ao);
                #pragma unroll
                for (int nt = 0; nt < 2; ++nt) {
                    mma16816(acc[mt][nt], Ah, bh[nt][0], bh[nt][1]);
                    mma16816(acc[mt][nt], Ah, bl[nt][0], bl[nt][1]);
                    mma16816(acc[mt][nt], Al, bh[nt][0], bh[nt][1]);
                }
            }
        }
        #pragma unroll
        for (int mt = 0; mt < 8; ++mt) {
            const int er0 = mt * 16 + g, er1 = er0 + 8;
            #pragma unroll
            for (int nt = 0; nt < 2; ++nt) {
                const int n = nbase + nt * 8 + tg * 2;
                uint32_t hw, lw;
                bfsplit2(fmaxf(acc[mt][nt][0], 0.f), fmaxf(acc[mt][nt][1], 0.f), hw, lw);
                *reinterpret_cast<uint32_t*>(smc + OFF_HH + er0 * 272 + n * 2) = hw;
                *reinterpret_cast<uint32_t*>(smc + OFF_HL + er0 * 272 + n * 2) = lw;
                bfsplit2(fmaxf(acc[mt][nt][2], 0.f), fmaxf(acc[mt][nt][3], 0.f), hw, lw);
                *reinterpret_cast<uint32_t*>(smc + OFF_HH + er1 * 272 + n * 2) = hw;
                *reinterpret_cast<uint32_t*>(smc + OFF_HL + er1 * 272 + n * 2) = lw;
            }
        }
        __syncthreads();

        float acc2[8][4];
        #pragma unroll
        for (int mt = 0; mt < 8; ++mt)
            #pragma unroll
            for (int j = 0; j < 4; ++j) acc2[mt][j] = 0.f;

        #pragma unroll
        for (int kt = 0; kt < 8; ++kt) {
            const int k0 = kt * 16;
            const uint32_t bo = (uint32_t)(((ncol0 + g) * 136 + k0 + tg * 2) * 2);
            const uint32_t bh0 = *reinterpret_cast<const uint32_t*>(smc + OFF_W2H + bo);
            const uint32_t bh1 = *reinterpret_cast<const uint32_t*>(smc + OFF_W2H + bo + 16);
            const uint32_t bl0 = *reinterpret_cast<const uint32_t*>(smc + OFF_W2L + bo);
            const uint32_t bl1 = *reinterpret_cast<const uint32_t*>(smc + OFF_W2L + bo + 16);
            #pragma unroll
            for (int mt = 0; mt < 8; ++mt) {
                const uint32_t ao = (uint32_t)(((mt * 16 + (qq & 1) * 8 + lr) * 136
                                                + k0 + (qq >> 1) * 8) * 2);
                uint32_t Ah[4], Al[4];
                ldmx4(Ah, sb + OFF_HH + ao);
                ldmx4(Al, sb + OFF_HL + ao);
                mma16816(acc2[mt], Ah, bh0, bh1);
                mma16816(acc2[mt], Ah, bl0, bl1);
                mma16816(acc2[mt], Al, bh0, bh1);
            }
        }
        {
            const int n = ncol0 + tg * 2;
            const float b0 = sB2[n], b1 = sB2[n + 1];
            #pragma unroll
            for (int mt = 0; mt < 8; ++mt) {
                const int er0 = mt * 16 + g, er1 = er0 + 8;
                const int r0 = sRid[er0], r1 = sRid[er1];
                atomicAdd(&g_agg[(size_t)r0 * 64 + n],     fmaxf(acc2[mt][0] + b0, 0.f));
                atomicAdd(&g_agg[(size_t)r0 * 64 + n + 1], fmaxf(acc2[mt][1] + b1, 0.f));
                atomicAdd(&g_agg[(size_t)r1 * 64 + n],     fmaxf(acc2[mt][2] + b0, 0.f));
                atomicAdd(&g_agg[(size_t)r1 * 64 + n + 1], fmaxf(acc2[mt][3] + b1, 0.f));
            }
        }
    }
}

// =====================================================================
// Kernel 3: node update MLP via warp-MMA (same machinery as edge kernel).
// 128-node tiles, 256 threads (8 warps), persistent 148 blocks.
//   X = [nodes || agg]  [128 x 128] bf16 hi/lo (stride 136)
//   GEMM1: h = relu(X @ W1 + b1)   -> reuses X smem buffer
//   GEMM2: y = h @ W2 + b2         -> fp32 smem
//   LayerNorm + residual (nodes reloaded from L2)
// =====================================================================
#define NOFF_B1   0
#define NOFF_B2   512
#define NOFF_LNS  768
#define NOFF_LNO  1024
#define NOFF_W1H  1280
#define NOFF_W1L  (NOFF_W1H + 34816)
#define NOFF_W2H  (NOFF_W1L + 34816)
#define NOFF_W2L  (NOFF_W2H + 17408)
#define NOFF_XH   (NOFF_W2L + 17408)   // X tile; reused as h after GEMM1
#define NOFF_XL   (NOFF_XH  + 34816)
#define NOFF_Y    (NOFF_XL  + 34816)   // 128 x 68 f32
#define NODE_SMEM_BYTES (NOFF_Y + 34816)   // 210176

__global__ __launch_bounds__(256, 1)
void node_mma_kernel(const float* __restrict__ nodes,
                     const float* __restrict__ node_W1,
                     const float* __restrict__ node_b1,
                     const float* __restrict__ node_W2,
                     const float* __restrict__ node_b2,
                     const float* __restrict__ ln_scale,
                     const float* __restrict__ ln_offset,
                     float* __restrict__ out)
{
    extern __shared__ char smc[];
    const uint32_t sb = smem_u32(smc);
    const int tid  = threadIdx.x;
    const int warp = tid >> 5;
    const int lane = tid & 31;
    const int g    = lane >> 2;
    const int tg   = lane & 3;
    const int qq   = lane >> 3;
    const int lr   = lane & 7;

    float* sB1  = reinterpret_cast<float*>(smc + NOFF_B1);
    float* sB2  = reinterpret_cast<float*>(smc + NOFF_B2);
    float* sLNs = reinterpret_cast<float*>(smc + NOFF_LNS);
    float* sLNo = reinterpret_cast<float*>(smc + NOFF_LNO);
    float* sY   = reinterpret_cast<float*>(smc + NOFF_Y);

    if (tid < 128) sB1[tid] = node_b1[tid];
    if (tid < 64) { sB2[tid] = node_b2[tid]; sLNs[tid] = ln_scale[tid]; sLNo[tid] = ln_offset[tid]; }

    // W1^T [n=128][k=128] bf16 hi/lo, stride 136
    for (int i = tid; i < 128 * 128; i += 256) {
        const int n = i >> 7, k = i & 127;
        const float w = node_W1[k * 128 + n];
        const __nv_bfloat16 h = __float2bfloat16_rn(w);
        const __nv_bfloat16 l = __float2bfloat16_rn(w - __bfloat162float(h));
        *reinterpret_cast<__nv_bfloat16*>(smc + NOFF_W1H + (n * 136 + k) * 2) = h;
        *reinterpret_cast<__nv_bfloat16*>(smc + NOFF_W1L + (n * 136 + k) * 2) = l;
    }
    // W2^T [n=64][k=128] bf16 hi/lo, stride 136
    for (int i = tid; i < 64 * 128; i += 256) {
        const int n = i >> 7, k = i & 127;
        const float w = node_W2[k * 64 + n];
        const __nv_bfloat16 h = __float2bfloat16_rn(w);
        const __nv_bfloat16 l = __float2bfloat16_rn(w - __bfloat162float(h));
        *reinterpret_cast<__nv_bfloat16*>(smc + NOFF_W2H + (n * 136 + k) * 2) = h;
        *reinterpret_cast<__nv_bfloat16*>(smc + NOFF_W2L + (n * 136 + k) * 2) = l;
    }

    const int nbase = warp * 16;   // GEMM1 n-strip
    const int ncol0 = warp * 8;    // GEMM2 n-strip
    const int numTiles = (N_NODES + 127) / 128;  // 782

    for (int tile = blockIdx.x; tile < numTiles; tile += gridDim.x) {
        const int n0 = tile * 128;
        __syncthreads();

        // ---- stage X tile: row=tid>>1, half=tid&1 (64 cols each) ----
        {
            const int row  = tid >> 1;
            const int half = tid & 1;
            const int n    = n0 + row;
            const bool valid = n < N_NODES;
            const float* src = half ? &g_agg[(size_t)n * 64] : &nodes[(size_t)n * 64];
            const uint32_t base = (uint32_t)(row * 272 + half * 128);
            #pragma unroll
            for (int q = 0; q < 8; ++q) {
                float4 f0 = valid ? reinterpret_cast<const float4*>(src)[2 * q]
                                  : make_float4(0.f, 0.f, 0.f, 0.f);
                float4 f1 = valid ? reinterpret_cast<const float4*>(src)[2 * q + 1]
                                  : make_float4(0.f, 0.f, 0.f, 0.f);
                uint32_t hi[4], lo[4];
                bfsplit2(f0.x, f0.y, hi[0], lo[0]);
                bfsplit2(f0.z, f0.w, hi[1], lo[1]);
                bfsplit2(f1.x, f1.y, hi[2], lo[2]);
                bfsplit2(f1.z, f1.w, hi[3], lo[3]);
                *reinterpret_cast<uint4*>(smc + NOFF_XH + base + q * 16) =
                    make_uint4(hi[0], hi[1], hi[2], hi[3]);
                *reinterpret_cast<uint4*>(smc + NOFF_XL + base + q * 16) =
                    make_uint4(lo[0], lo[1], lo[2], lo[3]);
            }
        }
        __syncthreads();

        // ---- GEMM1: [128x128] = X @ W1 + b1 ----
        float acc[8][2][4];
        #pragma unroll
        for (int mt = 0; mt < 8; ++mt)
            #pragma unroll
            for (int nt = 0; nt < 2; ++nt) {
                const int n = nbase + nt * 8 + tg * 2;
                acc[mt][nt][0] = sB1[n];
                acc[mt][nt][1] = sB1[n + 1];
                acc[mt][nt][2] = sB1[n];
                acc[mt][nt][3] = sB1[n + 1];
            }
        #pragma unroll
        for (int kt = 0; kt < 8; ++kt) {
            const int k0 = kt * 16;
            uint32_t bh[2][2], bl[2][2];
            #pragma unroll
            for (int nt = 0; nt < 2; ++nt) {
                const uint32_t bo = (uint32_t)(((nbase + nt * 8 + g) * 136 + k0 + tg * 2) * 2);
                bh[nt][0] = *reinterpret_cast<const uint32_t*>(smc + NOFF_W1H + bo);
                bh[nt][1] = *reinterpret_cast<const uint32_t*>(smc + NOFF_W1H + bo + 16);
                bl[nt][0] = *reinterpret_cast<const uint32_t*>(smc + NOFF_W1L + bo);
                bl[nt][1] = *reinterpret_cast<const uint32_t*>(smc + NOFF_W1L + bo + 16);
            }
            #pragma unroll
            for (int mt = 0; mt < 8; ++mt) {
                const uint32_t ao = (uint32_t)(((mt * 16 + (qq & 1) * 8 + lr) * 136
                                                + k0 + (qq >> 1) * 8) * 2);
                uint32_t Ah[4], Al[4];
                ldmx4(Ah, sb + NOFF_XH + ao);
                ldmx4(Al, sb + NOFF_XL + ao);
                #pragma unroll
                for (int nt = 0; nt < 2; ++nt) {
                    mma16816(acc[mt][nt], Ah, bh[nt][0], bh[nt][1]);
                    mma16816(acc[mt][nt], Ah, bl[nt][0], bl[nt][1]);
                    mma16816(acc[mt][nt], Al, bh[nt][0], bh[nt][1]);
                }
            }
        }
        __syncthreads();   // all warps done reading X before h overwrites it

        // ---- epilogue1: relu -> bf16 hi/lo h into X buffer ----
        #pragma unroll
        for (int mt = 0; mt < 8; ++mt) {
            const int er0 = mt * 16 + g, er1 = er0 + 8;
            #pragma unroll
            for (int nt = 0; nt < 2; ++nt) {
                const int n = nbase + nt * 8 + tg * 2;
                uint32_t hw, lw;
                bfsplit2(fmaxf(acc[mt][nt][0], 0.f), fmaxf(acc[mt][nt][1], 0.f), hw, lw);
                *reinterpret_cast<uint32_t*>(smc + NOFF_XH + er0 * 272 + n * 2) = hw;
                *reinterpret_cast<uint32_t*>(smc + NOFF_XL + er0 * 272 + n * 2) = lw;
                bfsplit2(fmaxf(acc[mt][nt][2], 0.f), fmaxf(acc[mt][nt][3], 0.f), hw, lw);
                *reinterpret_cast<uint32_t*>(smc + NOFF_XH + er1 * 272 + n * 2) = hw;
                *reinterpret_cast<uint32_t*>(smc + NOFF_XL + er1 * 272 + n * 2) = lw;
            }
        }
        __syncthreads();

        // ---- GEMM2: y[128x64] = h @ W2 + b2 ----
        float acc2[8][4];
        {
            const int n = ncol0 + tg * 2;
            const float b0 = sB2[n], b1v = sB2[n + 1];
            #pragma unroll
            for (int mt = 0; mt < 8; ++mt) {
                acc2[mt][0] = b0; acc2[mt][1] = b1v;
                acc2[mt][2] = b0; acc2[mt][3] = b1v;
            }
        }
        #pragma unroll
        for (int kt = 0; kt < 8; ++kt) {
            const int k0 = kt * 16;
            const uint32_t bo = (uint32_t)(((ncol0 + g) * 136 + k0 + tg * 2) * 2);
            const uint32_t bh0 = *reinterpret_cast<const uint32_t*>(smc + NOFF_W2H + bo);
            const uint32_t bh1 = *reinterpret_cast<const uint32_t*>(smc + NOFF_W2H + bo + 16);
            const uint32_t bl0 = *reinterpret_cast<const uint32_t*>(smc + NOFF_W2L + bo);
            const uint32_t bl1 = *reinterpret_cast<const uint32_t*>(smc + NOFF_W2L + bo + 16);
            #pragma unroll
            for (int mt = 0; mt < 8; ++mt) {
                const uint32_t ao = (uint32_t)(((mt * 16 + (qq & 1) * 8 + lr) * 136
                                                + k0 + (qq >> 1) * 8) * 2);
                uint32_t Ah[4], Al[4];
                ldmx4(Ah, sb + NOFF_XH + ao);
                ldmx4(Al, sb + NOFF_XL + ao);
                mma16816(acc2[mt], Ah, bh0, bh1);
                mma16816(acc2[mt], Ah, bl0, bl1);
                mma16816(acc2[mt], Al, bh0, bh1);
            }
        }
        // ---- store y fp32 ----
        {
            const int n = ncol0 + tg * 2;
            #pragma unroll
            for (int mt = 0; mt < 8; ++mt) {
                const int er0 = mt * 16 + g, er1 = er0 + 8;
                sY[er0 * 68 + n]     = acc2[mt][0];
                sY[er0 * 68 + n + 1] = acc2[mt][1];
                sY[er1 * 68 + n]     = acc2[mt][2];
                sY[er1 * 68 + n + 1] = acc2[mt][3];
            }
        }
        __syncthreads();

        // ---- LayerNorm + residual: 8 warps x 16 rows ----
        #pragma unroll
        for (int q = 0; q < 16; ++q) {
            const int i = warp * 16 + q;
            const int n = n0 + i;
            if (n >= N_NODES) break;
            const float v0 = sY[i * 68 + lane];
            const float v1 = sY[i * 68 + 32 + lane];
            float s  = v0 + v1;
            float sq = v0 * v0 + v1 * v1;
            #pragma unroll
            for (int off = 16; off; off >>= 1) {
                s  += __shfl_xor_sync(0xffffffffu, s,  off);
                sq += __shfl_xor_sync(0xffffffffu, sq, off);
            }
            const float mean = s * (1.f / 64.f);
            const float var  = sq * (1.f / 64.f) - mean * mean;
            const float rstd = rsqrtf(var + LN_EPS);
            out[(size_t)n * 64 + lane] =
                nodes[(size_t)n * 64 + lane] + (v0 - mean) * rstd * sLNs[lane] + sLNo[lane];
            out[(size_t)n * 64 + 32 + lane] =
                nodes[(size_t)n * 64 + 32 + lane] + (v1 - mean) * rstd * sLNs[32 + lane] + sLNo[32 + lane];
        }
    }
}

// =====================================================================
extern "C" void kernel_launch(void* const* d_in, const int* in_sizes, int n_in,
                              void* d_out, int out_size) {
    (void)in_sizes; (void)n_in; (void)out_size;
    const float* nodes     = (const float*)d_in[0];
    const float* edges     = (const float*)d_in[1];
    const int*   senders   = (const int*)d_in[2];
    const int*   receivers = (const int*)d_in[3];
    const float* msg_W1    = (const float*)d_in[4];
    const float* msg_b1    = (const float*)d_in[5];
    const float* msg_W2    = (const float*)d_in[6];
    const float* msg_b2    = (const float*)d_in[7];
    const float* node_W1   = (const float*)d_in[8];
    const float* node_b1   = (const float*)d_in[9];
    const float* node_W2   = (const float*)d_in[10];
    const float* node_b2   = (const float*)d_in[11];
    const float* ln_scale  = (const float*)d_in[12];
    const float* ln_offset = (const float*)d_in[13];
    float* out = (float*)d_out;

    cudaFuncSetAttribute(proj_kernel, cudaFuncAttributeMaxDynamicSharedMemorySize, (128 * 128 + 128) * 4);
    cudaFuncSetAttribute(edge_kernel, cudaFuncAttributeMaxDynamicSharedMemorySize, EDGE_SMEM_BYTES);
    cudaFuncSetAttribute(node_mma_kernel, cudaFuncAttributeMaxDynamicSharedMemorySize, NODE_SMEM_BYTES);

    zero_agg_kernel<<<256, 256>>>();
    proj_kernel<<<444, 256, (128 * 128 + 128) * 4>>>(nodes, msg_W1, msg_b1);
    edge_kernel<<<148, 256, EDGE_SMEM_BYTES>>>(edges, senders, receivers, msg_W1, msg_W2, msg_b2);
    node_mma_kernel<<<148, 256, NODE_SMEM_BYTES>>>(nodes, node_W1, node_b1, node_W2, node_b2,
                                                   ln_scale, ln_offset, out);
}

// round 11
// speedup vs baseline: 4.4509x; 1.0073x over previous
#include <cuda_runtime.h>
#include <cuda_bf16.h>
#include <cstdint>

// ---------------- fixed problem shapes ----------------
#define N_NODES 100000
#define D 64
#define E_EDGES 1600000
#define MSG_H 128
#define MSG_OUT 64
#define NODE_H 128
#define LN_EPS 1e-5f

// ---------------- device scratch ----------------
__device__ __align__(16) float g_Ps[(size_t)N_NODES * 128];  // nodes @ W1[0:64,:]
__device__ __align__(16) float g_Pr[(size_t)N_NODES * 128];  // nodes @ W1[64:128,:] + b1
__device__ __align__(16) float g_agg[(size_t)N_NODES * 64];  // segment-sum of messages

// =====================================================================
// warp-MMA helpers (sm_80 baseline features -> compile for compute_103)
// =====================================================================
__device__ __forceinline__ uint32_t smem_u32(const void* p) {
    uint32_t a;
    asm("{ .reg .u64 t; cvta.to.shared.u64 t, %1; cvt.u32.u64 %0, t; }" : "=r"(a) : "l"(p));
    return a;
}

__device__ __forceinline__ void ldmx4(uint32_t* r, uint32_t addr) {
    asm volatile("ldmatrix.sync.aligned.m8n8.x4.shared.b16 {%0,%1,%2,%3}, [%4];"
                 : "=r"(r[0]), "=r"(r[1]), "=r"(r[2]), "=r"(r[3]) : "r"(addr));
}

__device__ __forceinline__ void mma16816(float* d, const uint32_t* a, uint32_t b0, uint32_t b1) {
    asm volatile(
        "mma.sync.aligned.m16n8k16.row.col.f32.bf16.bf16.f32 "
        "{%0,%1,%2,%3}, {%4,%5,%6,%7}, {%8,%9}, {%0,%1,%2,%3};"
        : "+f"(d[0]), "+f"(d[1]), "+f"(d[2]), "+f"(d[3])
        : "r"(a[0]), "r"(a[1]), "r"(a[2]), "r"(a[3]), "r"(b0), "r"(b1));
}

__device__ __forceinline__ void bfsplit2(float x0, float x1, uint32_t& hi, uint32_t& lo) {
    __nv_bfloat162 h = __floats2bfloat162_rn(x0, x1);
    float r0 = x0 - __low2float(h);
    float r1 = x1 - __high2float(h);
    __nv_bfloat162 l = __floats2bfloat162_rn(r0, r1);
    hi = reinterpret_cast<uint32_t&>(h);
    lo = reinterpret_cast<uint32_t&>(l);
}

// =====================================================================
// Kernel 0: zero aggregation buffer
// =====================================================================
__global__ void zero_agg_kernel() {
    float4* p = reinterpret_cast<float4*>(g_agg);
    const int n4 = N_NODES * 64 / 4;
    for (int i = blockIdx.x * blockDim.x + threadIdx.x; i < n4; i += gridDim.x * blockDim.x)
        p[i] = make_float4(0.f, 0.f, 0.f, 0.f);
}

// =====================================================================
// Kernel 1: node projections (fp32 FFMA; 3.3 GFLOP total)
// =====================================================================
__global__ __launch_bounds__(256, 3)
void proj_kernel(const float* __restrict__ nodes,
                 const float* __restrict__ msg_W1,
                 const float* __restrict__ msg_b1)
{
    extern __shared__ float sm[];
    float* sW = sm;
    float* sN = sm + 128 * 128;

    const int tid = threadIdx.x;
    for (int i = tid; i < 128 * 128; i += 256) sW[i] = msg_W1[i];
    __syncthreads();

    const int sub = tid >> 7;
    const int c   = tid & 127;
    const float bias = msg_b1[c];

    const int numPairs = N_NODES / 2;
    for (int p = blockIdx.x; p < numPairs; p += gridDim.x) {
        const int n0 = p * 2;
        if (tid < 128) sN[tid] = nodes[(size_t)n0 * 64 + tid];
        __syncthreads();
        float as = 0.f, ar = 0.f;
        const float* nr = &sN[sub * 64];
        #pragma unroll 8
        for (int k = 0; k < 64; ++k) {
            const float a = nr[k];
            as = fmaf(a, sW[k * 128 + c], as);
            ar = fmaf(a, sW[(64 + k) * 128 + c], ar);
        }
        const int n = n0 + sub;
        g_Ps[(size_t)n * 128 + c] = as;
        g_Pr[(size_t)n * 128 + c] = ar + bias;
        __syncthreads();
    }
}

// =====================================================================
// Kernel 2: edge message MLP via warp-level bf16-split mma.sync.
// R11: 512 threads (16 warps), warp = (mw, nw) 2x8 decomposition.
//   mw: which 64-edge half; nw: 16-col strip (GEMM1) / 8-col (GEMM2).
//   4 warps per SMSP -> hide ldmatrix/L2-gather latency under HMMA.
// =====================================================================
#define OFF_B2   0
#define OFF_SID  256
#define OFF_RID  768
#define OFF_AH   1280
#define OFF_AL   (OFF_AH  + 18432)
#define OFF_W1H  (OFF_AL  + 18432)
#define OFF_W1L  (OFF_W1H + 18432)
#define OFF_W2H  (OFF_W1L + 18432)
#define OFF_W2L  (OFF_W2H + 17408)
#define OFF_HH   (OFF_W2L + 17408)
#define OFF_HL   (OFF_HH  + 34816)
#define EDGE_SMEM_BYTES (OFF_HL + 34816)   // 179456 bytes

__global__ __launch_bounds__(512, 1)
void edge_kernel(const float* __restrict__ edges,
                 const int* __restrict__ senders,
                 const int* __restrict__ receivers,
                 const float* __restrict__ msg_W1,
                 const float* __restrict__ msg_W2,
                 const float* __restrict__ msg_b2)
{
    extern __shared__ char smc[];
    const uint32_t sb = smem_u32(smc);
    const int tid  = threadIdx.x;
    const int warp = tid >> 5;        // 0..15
    const int lane = tid & 31;
    const int mw   = warp >> 3;       // 0..1  : 64-edge m-half
    const int nw   = warp & 7;        // 0..7  : n-strip
    const int g    = lane >> 2;       // groupID
    const int tg   = lane & 3;        // threadID-in-group
    const int qq   = lane >> 3;       // ldmatrix quadrant
    const int lr   = lane & 7;        // row within quadrant

    int* sSid = reinterpret_cast<int*>(smc + OFF_SID);
    int* sRid = reinterpret_cast<int*>(smc + OFF_RID);
    float* sB2 = reinterpret_cast<float*>(smc + OFF_B2);

    if (tid < 64) sB2[tid] = msg_b2[tid];

    // ---- stage W1e^T as [n=128][k=64] bf16 hi/lo, stride 72 ----
    for (int i = tid; i < 128 * 64; i += 512) {
        const int n = i >> 6, k = i & 63;
        const float w = msg_W1[(128 + k) * 128 + n];
        const __nv_bfloat16 h = __float2bfloat16_rn(w);
        const __nv_bfloat16 l = __float2bfloat16_rn(w - __bfloat162float(h));
        *reinterpret_cast<__nv_bfloat16*>(smc + OFF_W1H + (n * 72 + k) * 2) = h;
        *reinterpret_cast<__nv_bfloat16*>(smc + OFF_W1L + (n * 72 + k) * 2) = l;
    }
    // ---- stage W2^T as [n=64][k=128] bf16 hi/lo, stride 136 ----
    for (int i = tid; i < 64 * 128; i += 512) {
        const int n = i >> 7, k = i & 127;
        const float w = msg_W2[k * 64 + n];
        const __nv_bfloat16 h = __float2bfloat16_rn(w);
        const __nv_bfloat16 l = __float2bfloat16_rn(w - __bfloat162float(h));
        *reinterpret_cast<__nv_bfloat16*>(smc + OFF_W2H + (n * 136 + k) * 2) = h;
        *reinterpret_cast<__nv_bfloat16*>(smc + OFF_W2L + (n * 136 + k) * 2) = l;
    }

    const int nbase = nw * 16;   // GEMM1 n-strip
    const int ncol0 = nw * 8;    // GEMM2 n-strip
    const int mbase = mw * 4;    // m-tile offset (16-row units)

    const int numTiles = E_EDGES / 128;  // 12500
    for (int tile = blockIdx.x; tile < numTiles; tile += gridDim.x) {
        const int e0 = tile * 128;
        __syncthreads();  // prior tile's smem reads complete

        // ---- stage edge tile [128][64] -> bf16 hi/lo (stride 72) ----
        {
            const int c = tid;                        // 0..511 float4 tasks
            const int row = c >> 2, q = c & 3;        // q: 16-float chunk
            const float4* src = reinterpret_cast<const float4*>(
                &edges[(size_t)(e0 + row) * 64 + q * 16]);
            uint32_t hi[8], lo[8];
            #pragma unroll
            for (int j = 0; j < 4; ++j) {
                const float4 f = src[j];
                bfsplit2(f.x, f.y, hi[2 * j],     lo[2 * j]);
                bfsplit2(f.z, f.w, hi[2 * j + 1], lo[2 * j + 1]);
            }
            char* dh = smc + OFF_AH + row * 144 + q * 32;
            char* dl = smc + OFF_AL + row * 144 + q * 32;
            *reinterpret_cast<uint4*>(dh)      = make_uint4(hi[0], hi[1], hi[2], hi[3]);
            *reinterpret_cast<uint4*>(dh + 16) = make_uint4(hi[4], hi[5], hi[6], hi[7]);
            *reinterpret_cast<uint4*>(dl)      = make_uint4(lo[0], lo[1], lo[2], lo[3]);
            *reinterpret_cast<uint4*>(dl + 16) = make_uint4(lo[4], lo[5], lo[6], lo[7]);
        }
        // ---- stage sender/receiver ids ----
        if (tid < 128) sSid[tid] = senders[e0 + tid];
        else if (tid < 256) sRid[tid - 128] = receivers[e0 + tid - 128];
        __syncthreads();

        // ================= GEMM1 =================
        // acc init: Ps[s] + Pr[r] gathers (float2 per reg pair)
        float acc[4][2][4];
        #pragma unroll
        for (int mt = 0; mt < 4; ++mt) {
            const int er0 = (mbase + mt) * 16 + g, er1 = er0 + 8;
            const int s0 = sSid[er0], r0 = sRid[er0];
            const int s1 = sSid[er1], r1 = sRid[er1];
            #pragma unroll
            for (int nt = 0; nt < 2; ++nt) {
                const int n = nbase + nt * 8 + tg * 2;
                const float2 a0 = *reinterpret_cast<const float2*>(&g_Ps[(size_t)s0 * 128 + n]);
                const float2 b0 = *reinterpret_cast<const float2*>(&g_Pr[(size_t)r0 * 128 + n]);
                const float2 a1 = *reinterpret_cast<const float2*>(&g_Ps[(size_t)s1 * 128 + n]);
                const float2 b1 = *reinterpret_cast<const float2*>(&g_Pr[(size_t)r1 * 128 + n]);
                acc[mt][nt][0] = a0.x + b0.x;
                acc[mt][nt][1] = a0.y + b0.y;
                acc[mt][nt][2] = a1.x + b1.x;
                acc[mt][nt][3] = a1.y + b1.y;
            }
        }
        // K loop (K=64, 4 ksteps of 16)
        #pragma unroll
        for (int kt = 0; kt < 4; ++kt) {
            const int k0 = kt * 16;
            uint32_t bh[2][2], bl[2][2];
            #pragma unroll
            for (int nt = 0; nt < 2; ++nt) {
                const uint32_t bo = (uint32_t)(((nbase + nt * 8 + g) * 72 + k0 + tg * 2) * 2);
                bh[nt][0] = *reinterpret_cast<const uint32_t*>(smc + OFF_W1H + bo);
                bh[nt][1] = *reinterpret_cast<const uint32_t*>(smc + OFF_W1H + bo + 16);
                bl[nt][0] = *reinterpret_cast<const uint32_t*>(smc + OFF_W1L + bo);
                bl[nt][1] = *reinterpret_cast<const uint32_t*>(smc + OFF_W1L + bo + 16);
            }
            #pragma unroll
            for (int mt = 0; mt < 4; ++mt) {
                const uint32_t ao = (uint32_t)((((mbase + mt) * 16 + (qq & 1) * 8 + lr) * 72
                                                + k0 + (qq >> 1) * 8) * 2);
                uint32_t Ah[4], Al[4];
                ldmx4(Ah, sb + OFF_AH + ao);
                ldmx4(Al, sb + OFF_AL + ao);
                #pragma unroll
                for (int nt = 0; nt < 2; ++nt) {
                    mma16816(acc[mt][nt], Ah, bh[nt][0], bh[nt][1]);
                    mma16816(acc[mt][nt], Ah, bl[nt][0], bl[nt][1]);
                    mma16816(acc[mt][nt], Al, bh[nt][0], bh[nt][1]);
                }
            }
        }
        // epilogue1: relu -> bf16 hi/lo h tile (stride 136 elems = 272 B)
        #pragma unroll
        for (int mt = 0; mt < 4; ++mt) {
            const int er0 = (mbase + mt) * 16 + g, er1 = er0 + 8;
            #pragma unroll
            for (int nt = 0; nt < 2; ++nt) {
                const int n = nbase + nt * 8 + tg * 2;
                uint32_t hw, lw;
                bfsplit2(fmaxf(acc[mt][nt][0], 0.f), fmaxf(acc[mt][nt][1], 0.f), hw, lw);
                *reinterpret_cast<uint32_t*>(smc + OFF_HH + er0 * 272 + n * 2) = hw;
                *reinterpret_cast<uint32_t*>(smc + OFF_HL + er0 * 272 + n * 2) = lw;
                bfsplit2(fmaxf(acc[mt][nt][2], 0.f), fmaxf(acc[mt][nt][3], 0.f), hw, lw);
                *reinterpret_cast<uint32_t*>(smc + OFF_HH + er1 * 272 + n * 2) = hw;
                *reinterpret_cast<uint32_t*>(smc + OFF_HL + er1 * 272 + n * 2) = lw;
            }
        }
        __syncthreads();

        // ================= GEMM2 ================= (M=128, N=64, K=128)
        float acc2[4][4];
        #pragma unroll
        for (int mt = 0; mt < 4; ++mt)
            #pragma unroll
            for (int j = 0; j < 4; ++j) acc2[mt][j] = 0.f;

        #pragma unroll
        for (int kt = 0; kt < 8; ++kt) {
            const int k0 = kt * 16;
            const uint32_t bo = (uint32_t)(((ncol0 + g) * 136 + k0 + tg * 2) * 2);
            const uint32_t bh0 = *reinterpret_cast<const uint32_t*>(smc + OFF_W2H + bo);
            const uint32_t bh1 = *reinterpret_cast<const uint32_t*>(smc + OFF_W2H + bo + 16);
            const uint32_t bl0 = *reinterpret_cast<const uint32_t*>(smc + OFF_W2L + bo);
            const uint32_t bl1 = *reinterpret_cast<const uint32_t*>(smc + OFF_W2L + bo + 16);
            #pragma unroll
            for (int mt = 0; mt < 4; ++mt) {
                const uint32_t ao = (uint32_t)((((mbase + mt) * 16 + (qq & 1) * 8 + lr) * 136
                                                + k0 + (qq >> 1) * 8) * 2);
                uint32_t Ah[4], Al[4];
                ldmx4(Ah, sb + OFF_HH + ao);
                ldmx4(Al, sb + OFF_HL + ao);
                mma16816(acc2[mt], Ah, bh0, bh1);
                mma16816(acc2[mt], Ah, bl0, bl1);
                mma16816(acc2[mt], Al, bh0, bh1);
            }
        }
        // epilogue2: + b2, relu, scatter-add
        {
            const int n = ncol0 + tg * 2;
            const float b0 = sB2[n], b1 = sB2[n + 1];
            #pragma unroll
            for (int mt = 0; mt < 4; ++mt) {
                const int er0 = (mbase + mt) * 16 + g, er1 = er0 + 8;
                const int r0 = sRid[er0], r1 = sRid[er1];
                atomicAdd(&g_agg[(size_t)r0 * 64 + n],     fmaxf(acc2[mt][0] + b0, 0.f));
                atomicAdd(&g_agg[(size_t)r0 * 64 + n + 1], fmaxf(acc2[mt][1] + b1, 0.f));
                atomicAdd(&g_agg[(size_t)r1 * 64 + n],     fmaxf(acc2[mt][2] + b0, 0.f));
                atomicAdd(&g_agg[(size_t)r1 * 64 + n + 1], fmaxf(acc2[mt][3] + b1, 0.f));
            }
        }
    }
}

// =====================================================================
// Kernel 3: node update MLP via warp-MMA (unchanged from R10, 94us)
// =====================================================================
#define NOFF_B1   0
#define NOFF_B2   512
#define NOFF_LNS  768
#define NOFF_LNO  1024
#define NOFF_W1H  1280
#define NOFF_W1L  (NOFF_W1H + 34816)
#define NOFF_W2H  (NOFF_W1L + 34816)
#define NOFF_W2L  (NOFF_W2H + 17408)
#define NOFF_XH   (NOFF_W2L + 17408)   // X tile; reused as h after GEMM1
#define NOFF_XL   (NOFF_XH  + 34816)
#define NOFF_Y    (NOFF_XL  + 34816)   // 128 x 68 f32
#define NODE_SMEM_BYTES (NOFF_Y + 34816)   // 210176

__global__ __launch_bounds__(256, 1)
void node_mma_kernel(const float* __restrict__ nodes,
                     const float* __restrict__ node_W1,
                     const float* __restrict__ node_b1,
                     const float* __restrict__ node_W2,
                     const float* __restrict__ node_b2,
                     const float* __restrict__ ln_scale,
                     const float* __restrict__ ln_offset,
                     float* __restrict__ out)
{
    extern __shared__ char smc[];
    const uint32_t sb = smem_u32(smc);
    const int tid  = threadIdx.x;
    const int warp = tid >> 5;
    const int lane = tid & 31;
    const int g    = lane >> 2;
    const int tg   = lane & 3;
    const int qq   = lane >> 3;
    const int lr   = lane & 7;

    float* sB1  = reinterpret_cast<float*>(smc + NOFF_B1);
    float* sB2  = reinterpret_cast<float*>(smc + NOFF_B2);
    float* sLNs = reinterpret_cast<float*>(smc + NOFF_LNS);
    float* sLNo = reinterpret_cast<float*>(smc + NOFF_LNO);
    float* sY   = reinterpret_cast<float*>(smc + NOFF_Y);

    if (tid < 128) sB1[tid] = node_b1[tid];
    if (tid < 64) { sB2[tid] = node_b2[tid]; sLNs[tid] = ln_scale[tid]; sLNo[tid] = ln_offset[tid]; }

    for (int i = tid; i < 128 * 128; i += 256) {
        const int n = i >> 7, k = i & 127;
        const float w = node_W1[k * 128 + n];
        const __nv_bfloat16 h = __float2bfloat16_rn(w);
        const __nv_bfloat16 l = __float2bfloat16_rn(w - __bfloat162float(h));
        *reinterpret_cast<__nv_bfloat16*>(smc + NOFF_W1H + (n * 136 + k) * 2) = h;
        *reinterpret_cast<__nv_bfloat16*>(smc + NOFF_W1L + (n * 136 + k) * 2) = l;
    }
    for (int i = tid; i < 64 * 128; i += 256) {
        const int n = i >> 7, k = i & 127;
        const float w = node_W2[k * 64 + n];
        const __nv_bfloat16 h = __float2bfloat16_rn(w);
        const __nv_bfloat16 l = __float2bfloat16_rn(w - __bfloat162float(h));
        *reinterpret_cast<__nv_bfloat16*>(smc + NOFF_W2H + (n * 136 + k) * 2) = h;
        *reinterpret_cast<__nv_bfloat16*>(smc + NOFF_W2L + (n * 136 + k) * 2) = l;
    }

    const int nbase = warp * 16;
    const int ncol0 = warp * 8;
    const int numTiles = (N_NODES + 127) / 128;  // 782

    for (int tile = blockIdx.x; tile < numTiles; tile += gridDim.x) {
        const int n0 = tile * 128;
        __syncthreads();

        {
            const int row  = tid >> 1;
            const int half = tid & 1;
            const int n    = n0 + row;
            const bool valid = n < N_NODES;
            const float* src = half ? &g_agg[(size_t)n * 64] : &nodes[(size_t)n * 64];
            const uint32_t base = (uint32_t)(row * 272 + half * 128);
            #pragma unroll
            for (int q = 0; q < 8; ++q) {
                float4 f0 = valid ? reinterpret_cast<const float4*>(src)[2 * q]
                                  : make_float4(0.f, 0.f, 0.f, 0.f);
                float4 f1 = valid ? reinterpret_cast<const float4*>(src)[2 * q + 1]
                                  : make_float4(0.f, 0.f, 0.f, 0.f);
                uint32_t hi[4], lo[4];
                bfsplit2(f0.x, f0.y, hi[0], lo[0]);
                bfsplit2(f0.z, f0.w, hi[1], lo[1]);
                bfsplit2(f1.x, f1.y, hi[2], lo[2]);
                bfsplit2(f1.z, f1.w, hi[3], lo[3]);
                *reinterpret_cast<uint4*>(smc + NOFF_XH + base + q * 16) =
                    make_uint4(hi[0], hi[1], hi[2], hi[3]);
                *reinterpret_cast<uint4*>(smc + NOFF_XL + base + q * 16) =
                    make_uint4(lo[0], lo[1], lo[2], lo[3]);
            }
        }
        __syncthreads();

        float acc[8][2][4];
        #pragma unroll
        for (int mt = 0; mt < 8; ++mt)
            #pragma unroll
            for (int nt = 0; nt < 2; ++nt) {
                const int n = nbase + nt * 8 + tg * 2;
                acc[mt][nt][0] = sB1[n];
                acc[mt][nt][1] = sB1[n + 1];
                acc[mt][nt][2] = sB1[n];
                acc[mt][nt][3] = sB1[n + 1];
            }
        #pragma unroll
        for (int kt = 0; kt < 8; ++kt) {
            const int k0 = kt * 16;
            uint32_t bh[2][2], bl[2][2];
            #pragma unroll
            for (int nt = 0; nt < 2; ++nt) {
                const uint32_t bo = (uint32_t)(((nbase + nt * 8 + g) * 136 + k0 + tg * 2) * 2);
                bh[nt][0] = *reinterpret_cast<const uint32_t*>(smc + NOFF_W1H + bo);
                bh[nt][1] = *reinterpret_cast<const uint32_t*>(smc + NOFF_W1H + bo + 16);
                bl[nt][0] = *reinterpret_cast<const uint32_t*>(smc + NOFF_W1L + bo);
                bl[nt][1] = *reinterpret_cast<const uint32_t*>(smc + NOFF_W1L + bo + 16);
            }
            #pragma unroll
            for (int mt = 0; mt < 8; ++mt) {
                const uint32_t ao = (uint32_t)(((mt * 16 + (qq & 1) * 8 + lr) * 136
                                                + k0 + (qq >> 1) * 8) * 2);
                uint32_t Ah[4], Al[4];
                ldmx4(Ah, sb + NOFF_XH + ao);
                ldmx4(Al, sb + NOFF_XL + ao);
                #pragma unroll
                for (int nt = 0; nt < 2; ++nt) {
                    mma16816(acc[mt][nt], Ah, bh[nt][0], bh[nt][1]);
                    mma16816(acc[mt][nt], Ah, bl[nt][0], bl[nt][1]);
                    mma16816(acc[mt][nt], Al, bh[nt][0], bh[nt][1]);
                }
            }
        }
        __syncthreads();

        #pragma unroll
        for (int mt = 0; mt < 8; ++mt) {
            const int er0 = mt * 16 + g, er1 = er0 + 8;
            #pragma unroll
            for (int nt = 0; nt < 2; ++nt) {
                const int n = nbase + nt * 8 + tg * 2;
                uint32_t hw, lw;
                bfsplit2(fmaxf(acc[mt][nt][0], 0.f), fmaxf(acc[mt][nt][1], 0.f), hw, lw);
                *reinterpret_cast<uint32_t*>(smc + NOFF_XH + er0 * 272 + n * 2) = hw;
                *reinterpret_cast<uint32_t*>(smc + NOFF_XL + er0 * 272 + n * 2) = lw;
                bfsplit2(fmaxf(acc[mt][nt][2], 0.f), fmaxf(acc[mt][nt][3], 0.f), hw, lw);
                *reinterpret_cast<uint32_t*>(smc + NOFF_XH + er1 * 272 + n * 2) = hw;
                *reinterpret_cast<uint32_t*>(smc + NOFF_XL + er1 * 272 + n * 2) = lw;
            }
        }
        __syncthreads();

        float acc2[8][4];
        {
            const int n = ncol0 + tg * 2;
            const float b0 = sB2[n], b1v = sB2[n + 1];
            #pragma unroll
            for (int mt = 0; mt < 8; ++mt) {
                acc2[mt][0] = b0; acc2[mt][1] = b1v;
                acc2[mt][2] = b0; acc2[mt][3] = b1v;
            }
        }
        #pragma unroll
        for (int kt = 0; kt < 8; ++kt) {
            const int k0 = kt * 16;
            const uint32_t bo = (uint32_t)(((ncol0 + g) * 136 + k0 + tg * 2) * 2);
            const uint32_t bh0 = *reinterpret_cast<const uint32_t*>(smc + NOFF_W2H + bo);
            const uint32_t bh1 = *reinterpret_cast<const uint32_t*>(smc + NOFF_W2H + bo + 16);
            const uint32_t bl0 = *reinterpret_cast<const uint32_t*>(smc + NOFF_W2L + bo);
            const uint32_t bl1 = *reinterpret_cast<const uint32_t*>(smc + NOFF_W2L + bo + 16);
            #pragma unroll
            for (int mt = 0; mt < 8; ++mt) {
                const uint32_t ao = (uint32_t)(((mt * 16 + (qq & 1) * 8 + lr) * 136
                                                + k0 + (qq >> 1) * 8) * 2);
                uint32_t Ah[4], Al[4];
                ldmx4(Ah, sb + NOFF_XH + ao);
                ldmx4(Al, sb + NOFF_XL + ao);
                mma16816(acc2[mt], Ah, bh0, bh1);
                mma16816(acc2[mt], Ah, bl0, bl1);
                mma16816(acc2[mt], Al, bh0, bh1);
            }
        }
        {
            const int n = ncol0 + tg * 2;
            #pragma unroll
            for (int mt = 0; mt < 8; ++mt) {
                const int er0 = mt * 16 + g, er1 = er0 + 8;
                sY[er0 * 68 + n]     = acc2[mt][0];
                sY[er0 * 68 + n + 1] = acc2[mt][1];
                sY[er1 * 68 + n]     = acc2[mt][2];
                sY[er1 * 68 + n + 1] = acc2[mt][3];
            }
        }
        __syncthreads();

        #pragma unroll
        for (int q = 0; q < 16; ++q) {
            const int i = warp * 16 + q;
            const int n = n0 + i;
            if (n >= N_NODES) break;
            const float v0 = sY[i * 68 + lane];
            const float v1 = sY[i * 68 + 32 + lane];
            float s  = v0 + v1;
            float sq = v0 * v0 + v1 * v1;
            #pragma unroll
            for (int off = 16; off; off >>= 1) {
                s  += __shfl_xor_sync(0xffffffffu, s,  off);
                sq += __shfl_xor_sync(0xffffffffu, sq, off);
            }
            const float mean = s * (1.f / 64.f);
            const float var  = sq * (1.f / 64.f) - mean * mean;
            const float rstd = rsqrtf(var + LN_EPS);
            out[(size_t)n * 64 + lane] =
                nodes[(size_t)n * 64 + lane] + (v0 - mean) * rstd * sLNs[lane] + sLNo[lane];
            out[(size_t)n * 64 + 32 + lane] =
                nodes[(size_t)n * 64 + 32 + lane] + (v1 - mean) * rstd * sLNs[32 + lane] + sLNo[32 + lane];
        }
    }
}

// =====================================================================
extern "C" void kernel_launch(void* const* d_in, const int* in_sizes, int n_in,
                              void* d_out, int out_size) {
    (void)in_sizes; (void)n_in; (void)out_size;
    const float* nodes     = (const float*)d_in[0];
    const float* edges     = (const float*)d_in[1];
    const int*   senders   = (const int*)d_in[2];
    const int*   receivers = (const int*)d_in[3];
    const float* msg_W1    = (const float*)d_in[4];
    const float* msg_b1    = (const float*)d_in[5];
    const float* msg_W2    = (const float*)d_in[6];
    const float* msg_b2    = (const float*)d_in[7];
    const float* node_W1   = (const float*)d_in[8];
    const float* node_b1   = (const float*)d_in[9];
    const float* node_W2   = (const float*)d_in[10];
    const float* node_b2   = (const float*)d_in[11];
    const float* ln_scale  = (const float*)d_in[12];
    const float* ln_offset = (const float*)d_in[13];
    float* out = (float*)d_out;

    cudaFuncSetAttribute(proj_kernel, cudaFuncAttributeMaxDynamicSharedMemorySize, (128 * 128 + 128) * 4);
    cudaFuncSetAttribute(edge_kernel, cudaFuncAttributeMaxDynamicSharedMemorySize, EDGE_SMEM_BYTES);
    cudaFuncSetAttribute(node_mma_kernel, cudaFuncAttributeMaxDynamicSharedMemorySize, NODE_SMEM_BYTES);

    zero_agg_kernel<<<256, 256>>>();
    proj_kernel<<<444, 256, (128 * 128 + 128) * 4>>>(nodes, msg_W1, msg_b1);
    edge_kernel<<<148, 512, EDGE_SMEM_BYTES>>>(edges, senders, receivers, msg_W1, msg_W2, msg_b2);
    node_mma_kernel<<<148, 256, NODE_SMEM_BYTES>>>(nodes, node_W1, node_b1, node_W2, node_b2,
                                                   ln_scale, ln_offset, out);
}